// round 9
// baseline (speedup 1.0000x reference)
#include <cuda_runtime.h>
#include <cstdint>

// ---------------- problem dimensions (fixed by the dataset) ----------------
#define PN1 100000
#define PE1 1600000
#define PD  128
#define PN2 1024
#define PE2 200000
#define PNB 30
#define GRP 6               // bases per group
#define NGRP 5              // 5 * 6 = 30 bases
#define NKT_G 384           // K-tiles per group GEMM: 6*1024/16
#define ZS_G 8              // split-K for group GEMM -> 48 tiles/split
#define KT_G (NKT_G / ZS_G) // 48
#define NKT_R 64            // K-tiles for root GEMM: 1024/16
#define ZS_R 2              // split-K
#define KT_R (NKT_R / ZS_R) // 32

// ---------------- device scratch (static, 16B-aligned, ~106 MB) ----------------
__device__ __align__(16) float g_deg1[PN1];
__device__ __align__(16) float g_agg1[(size_t)PN1 * PD];        // 51.2 MB
__device__ __align__(16) float g_deg2[PN2];
__device__ __align__(16) float g_A[(size_t)GRP * PN2 * PN2];    // 25.2 MB
__device__ __align__(16) float g_S[(size_t)GRP * PN2 * PN2];    // 25.2 MB
__device__ __align__(16) float g_h2[(size_t)PN2 * PN2];         // 4 MB
__device__ int g_is64;      // 1 if index buffers are int64, 0 if int32

// index load that works for both widths (flag set by probe_kernel)
__device__ __forceinline__ int load_idx(const void* p, size_t idx) {
    if (g_is64) return (int)((const long long*)p)[idx];
    return ((const int*)p)[idx];
}

// =====================================================================
// dtype probe: for int64 indices (< 2^31), every odd 32-bit word is 0.
// For int32 layout those words are dst indices — essentially never all zero.
// =====================================================================
__global__ void probe_kernel(const int* __restrict__ ei_words) {
    __shared__ int found;
    if (threadIdx.x == 0) found = 0;
    __syncthreads();
    for (int i = threadIdx.x; i < 4096; i += 256)
        if (ei_words[2 * i + 1] != 0) found = 1;
    __syncthreads();
    if (threadIdx.x == 0) g_is64 = found ? 0 : 1;
}

// =====================================================================
// zeroing kernels (kernel_launch stays launch-only)
// =====================================================================
__global__ void zero_main_kernel() {
    const size_t i = (size_t)blockIdx.x * blockDim.x + threadIdx.x;
    const float4 z = make_float4(0.f, 0.f, 0.f, 0.f);
    if (i < (size_t)PN1 * PD / 4)  ((float4*)g_agg1)[i] = z;   // 3,200,000
    if (i < PN1 / 4)               ((float4*)g_deg1)[i] = z;
    if (i < (size_t)PN2 * PN2 / 4) ((float4*)g_h2)[i] = z;
    if (i < PN2 / 4)               ((float4*)g_deg2)[i] = z;
}

__global__ void zero_A_kernel() {
    const size_t i = (size_t)blockIdx.x * blockDim.x + threadIdx.x;
    if (i < (size_t)GRP * PN2 * PN2 / 4)
        ((float4*)g_A)[i] = make_float4(0.f, 0.f, 0.f, 0.f);
}

// =====================================================================
// Part 1: STCConv
// =====================================================================

// one warp per edge: gather x[src] row (float4/lane), scalar-reduce into agg[dst]
__global__ void scatter1_kernel(const float* __restrict__ x,
                                const void* __restrict__ ei) {
    const unsigned gw = (blockIdx.x * blockDim.x + threadIdx.x) >> 5;
    const int lane = threadIdx.x & 31;
    if (gw >= PE1) return;
    const int s = load_idx(ei, gw);
    const int d = load_idx(ei, (size_t)PE1 + gw);
    float4 v = *(const float4*)(x + (size_t)s * PD + lane * 4);
    float* a = g_agg1 + (size_t)d * PD + lane * 4;
    atomicAdd(a + 0, v.x);
    atomicAdd(a + 1, v.y);
    atomicAdd(a + 2, v.z);
    atomicAdd(a + 3, v.w);
    if (lane == 0) atomicAdd(&g_deg1[d], 1.0f);
}

// fused: h = relu(agg/deg @ W + b); out1 = log_softmax(h).
// One warp per 8 rows; lane owns 4 output cols; W staged in 2 K-halves (32 KB smem).
__global__ __launch_bounds__(256) void linear1_kernel(const float* __restrict__ W,
                                                      const float* __restrict__ bias,
                                                      float* __restrict__ out1) {
    __shared__ float Ws[64 * 128];
    const int tid = threadIdx.x;
    const int lane = tid & 31;
    const int warp = tid >> 5;
    const int row0 = blockIdx.x * 64 + warp * 8;
    const int nrow = max(0, min(8, PN1 - row0));
    const float4 bv = *(const float4*)(bias + lane * 4);

    float acc[8][4];
#pragma unroll
    for (int r = 0; r < 8; r++) {
        acc[r][0] = bv.x; acc[r][1] = bv.y; acc[r][2] = bv.z; acc[r][3] = bv.w;
    }

#pragma unroll 1
    for (int half = 0; half < 2; half++) {
        __syncthreads();
        for (int i = tid; i < 2048; i += 256)
            ((float4*)Ws)[i] = ((const float4*)W)[half * 2048 + i];
        __syncthreads();
        for (int r = 0; r < nrow; r++) {
            const int row = row0 + r;
            const float invd = 1.0f / fmaxf(g_deg1[row], 1.0f);
            float4 v = *(const float4*)(g_agg1 + (size_t)row * PD +
                                        half * 64 + (lane & 15) * 4);
            v.x *= invd; v.y *= invd; v.z *= invd; v.w *= invd;
#pragma unroll
            for (int k4 = 0; k4 < 16; k4++) {
                float r0 = __shfl_sync(0xffffffffu, v.x, k4);
                float r1 = __shfl_sync(0xffffffffu, v.y, k4);
                float r2 = __shfl_sync(0xffffffffu, v.z, k4);
                float r3 = __shfl_sync(0xffffffffu, v.w, k4);
                const float* wp = Ws + (k4 * 4) * PD + lane * 4;
                float4 w0 = *(const float4*)(wp);
                float4 w1 = *(const float4*)(wp + PD);
                float4 w2 = *(const float4*)(wp + 2 * PD);
                float4 w3 = *(const float4*)(wp + 3 * PD);
                acc[r][0] += r0 * w0.x + r1 * w1.x + r2 * w2.x + r3 * w3.x;
                acc[r][1] += r0 * w0.y + r1 * w1.y + r2 * w2.y + r3 * w3.y;
                acc[r][2] += r0 * w0.z + r1 * w1.z + r2 * w2.z + r3 * w3.z;
                acc[r][3] += r0 * w0.w + r1 * w1.w + r2 * w2.w + r3 * w3.w;
            }
        }
    }

    for (int r = 0; r < nrow; r++) {
        float a0 = fmaxf(acc[r][0], 0.0f), a1 = fmaxf(acc[r][1], 0.0f);
        float a2 = fmaxf(acc[r][2], 0.0f), a3 = fmaxf(acc[r][3], 0.0f);
        float m = fmaxf(fmaxf(a0, a1), fmaxf(a2, a3));
#pragma unroll
        for (int o = 16; o; o >>= 1) m = fmaxf(m, __shfl_xor_sync(0xffffffffu, m, o));
        float s = __expf(a0 - m) + __expf(a1 - m) + __expf(a2 - m) + __expf(a3 - m);
#pragma unroll
        for (int o = 16; o; o >>= 1) s += __shfl_xor_sync(0xffffffffu, s, o);
        float lse = m + __logf(s);
        *(float4*)(out1 + (size_t)(row0 + r) * PD + lane * 4) =
            make_float4(a0 - lse, a1 - lse, a2 - lse, a3 - lse);
    }
}

// =====================================================================
// Part 2: RGCN with basis decomposition, densified in 5 groups of 6 bases
// =====================================================================

__global__ void deg2_kernel(const void* __restrict__ ei) {
    int e = blockIdx.x * blockDim.x + threadIdx.x;
    if (e < PE2) atomicAdd(&g_deg2[load_idx(ei, (size_t)PE2 + e)], 1.0f);
}

// A[b][d][s] += att[type][grp*6+b] / deg[d],  b in [0,6)
__global__ void build_A_kernel(const void* __restrict__ ei,
                               const void* __restrict__ et,
                               const float* __restrict__ att, int grp) {
    int e = blockIdx.x * blockDim.x + threadIdx.x;
    if (e >= PE2) return;
    const int s = load_idx(ei, e);
    const int d = load_idx(ei, (size_t)PE2 + e);
    const int t = load_idx(et, e);
    const float w = 1.0f / fmaxf(g_deg2[d], 1.0f);
    const float* ar = att + (size_t)t * PNB + grp * GRP;
    float* base = g_A + (size_t)d * PN2 + s;
#pragma unroll
    for (int b = 0; b < GRP; b++)
        atomicAdd(base + ((size_t)b << 20), ar[b] * w);
}

// batched fp32 GEMM: S[z] = A[z] @ X (z in [0,6)), 1024^3 each.
// 128x128 tile, BK=16, 256 threads, 8x8 microtile, double-buffered smem.
__global__ __launch_bounds__(256) void gemm1_kernel(const float* __restrict__ X) {
    const float* A = g_A + ((size_t)blockIdx.z << 20);
    float* C = g_S + ((size_t)blockIdx.z << 20);
    const int m0 = blockIdx.y * 128, n0 = blockIdx.x * 128;
    __shared__ float As[2][16][128];
    __shared__ float Bs[2][16][128];
    const int tid = threadIdx.x;
    const int tx = tid & 15, ty = tid >> 4;
    const int arow = tid >> 2, acol = (tid & 3) << 2;
    const int brow = tid >> 5, bcol = (tid & 31) << 2;

    float acc[8][8];
#pragma unroll
    for (int i = 0; i < 8; i++)
#pragma unroll
        for (int j = 0; j < 8; j++) acc[i][j] = 0.0f;

    const float* Ap0 = A + (size_t)(m0 + arow) * PN2 + acol;
    const float* Ap1 = A + (size_t)(m0 + arow + 64) * PN2 + acol;
    const float* Bp0 = X + (size_t)brow * PN2 + n0 + bcol;
    const float* Bp1 = X + (size_t)(brow + 8) * PN2 + n0 + bcol;

    float4 a0 = *(const float4*)Ap0;
    float4 a1 = *(const float4*)Ap1;
    float4 b0 = *(const float4*)Bp0;
    float4 b1 = *(const float4*)Bp1;
    As[0][acol + 0][arow] = a0.x; As[0][acol + 1][arow] = a0.y;
    As[0][acol + 2][arow] = a0.z; As[0][acol + 3][arow] = a0.w;
    As[0][acol + 0][arow + 64] = a1.x; As[0][acol + 1][arow + 64] = a1.y;
    As[0][acol + 2][arow + 64] = a1.z; As[0][acol + 3][arow + 64] = a1.w;
    *(float4*)&Bs[0][brow][bcol] = b0;
    *(float4*)&Bs[0][brow + 8][bcol] = b1;
    __syncthreads();

    const int NK = PN2 / 16;   // 64
    for (int t = 0; t < NK; t++) {
        const int buf = t & 1;
        if (t + 1 < NK) {
            const int k0 = (t + 1) * 16;
            a0 = *(const float4*)(Ap0 + k0);
            a1 = *(const float4*)(Ap1 + k0);
            b0 = *(const float4*)(Bp0 + (size_t)k0 * PN2);
            b1 = *(const float4*)(Bp1 + (size_t)k0 * PN2);
        }
#pragma unroll
        for (int k = 0; k < 16; k++) {
            float ra[8], rb[8];
            *(float4*)(ra)     = *(const float4*)&As[buf][k][ty * 4];
            *(float4*)(ra + 4) = *(const float4*)&As[buf][k][ty * 4 + 64];
            *(float4*)(rb)     = *(const float4*)&Bs[buf][k][tx * 4];
            *(float4*)(rb + 4) = *(const float4*)&Bs[buf][k][tx * 4 + 64];
#pragma unroll
            for (int i = 0; i < 8; i++)
#pragma unroll
                for (int j = 0; j < 8; j++) acc[i][j] += ra[i] * rb[j];
        }
        if (t + 1 < NK) {
            const int nb = buf ^ 1;
            As[nb][acol + 0][arow] = a0.x; As[nb][acol + 1][arow] = a0.y;
            As[nb][acol + 2][arow] = a0.z; As[nb][acol + 3][arow] = a0.w;
            As[nb][acol + 0][arow + 64] = a1.x; As[nb][acol + 1][arow + 64] = a1.y;
            As[nb][acol + 2][arow + 64] = a1.z; As[nb][acol + 3][arow + 64] = a1.w;
            *(float4*)&Bs[nb][brow][bcol] = b0;
            *(float4*)&Bs[nb][brow + 8][bcol] = b1;
        }
        __syncthreads();
    }
#pragma unroll
    for (int i = 0; i < 8; i++) {
        const int r = m0 + (ty << 2) + (i & 3) + ((i >> 2) << 6);
        float* crow = C + (size_t)r * PN2 + n0 + (tx << 2);
        *(float4*)crow = make_float4(acc[i][0], acc[i][1], acc[i][2], acc[i][3]);
        *(float4*)(crow + 64) = make_float4(acc[i][4], acc[i][5], acc[i][6], acc[i][7]);
    }
}

// split-K accumulating GEMM: h2 += A'(1024 x 16*nkt) @ B'(16*nkt x 1024).
// A' is blocked: K-tile kt lives at Abase + (kt>>6)<<20 + ((kt<<4)&1023), row stride 1024.
// Asrc == nullptr means "use g_S".
__global__ __launch_bounds__(256) void gemm_acc_kernel(const float* __restrict__ Asrc,
                                                       const float* __restrict__ Bsrc,
                                                       int kt_per_split) {
    const float* Abase = Asrc ? Asrc : (const float*)g_S;
    const int m0 = blockIdx.y * 128, n0 = blockIdx.x * 128;
    const int kt_base = blockIdx.z * kt_per_split;
    __shared__ float As[2][16][128];
    __shared__ float Bs[2][16][128];
    const int tid = threadIdx.x;
    const int tx = tid & 15, ty = tid >> 4;
    const int arow = tid >> 2, acol = (tid & 3) << 2;
    const int brow = tid >> 5, bcol = (tid & 31) << 2;

    float acc[8][8];
#pragma unroll
    for (int i = 0; i < 8; i++)
#pragma unroll
        for (int j = 0; j < 8; j++) acc[i][j] = 0.0f;

    auto getA = [&](int kt) -> const float* {
        const int k0 = kt << 4;
        return Abase + (((size_t)(k0 >> 10)) << 20) + (k0 & 1023);
    };
    auto getB = [&](int kt) -> const float* {
        return Bsrc + ((size_t)(kt << 4)) * PN2;
    };

    float4 a0, a1, b0, b1;
    {
        const float* Ab = getA(kt_base);
        const float* Bb = getB(kt_base);
        a0 = *(const float4*)(Ab + (size_t)(m0 + arow) * PN2 + acol);
        a1 = *(const float4*)(Ab + (size_t)(m0 + arow + 64) * PN2 + acol);
        b0 = *(const float4*)(Bb + (size_t)brow * PN2 + n0 + bcol);
        b1 = *(const float4*)(Bb + (size_t)(brow + 8) * PN2 + n0 + bcol);
    }
    As[0][acol + 0][arow] = a0.x; As[0][acol + 1][arow] = a0.y;
    As[0][acol + 2][arow] = a0.z; As[0][acol + 3][arow] = a0.w;
    As[0][acol + 0][arow + 64] = a1.x; As[0][acol + 1][arow + 64] = a1.y;
    As[0][acol + 2][arow + 64] = a1.z; As[0][acol + 3][arow + 64] = a1.w;
    *(float4*)&Bs[0][brow][bcol] = b0;
    *(float4*)&Bs[0][brow + 8][bcol] = b1;
    __syncthreads();

    for (int t = 0; t < kt_per_split; t++) {
        const int buf = t & 1;
        if (t + 1 < kt_per_split) {
            const float* Ab = getA(kt_base + t + 1);
            const float* Bb = getB(kt_base + t + 1);
            a0 = *(const float4*)(Ab + (size_t)(m0 + arow) * PN2 + acol);
            a1 = *(const float4*)(Ab + (size_t)(m0 + arow + 64) * PN2 + acol);
            b0 = *(const float4*)(Bb + (size_t)brow * PN2 + n0 + bcol);
            b1 = *(const float4*)(Bb + (size_t)(brow + 8) * PN2 + n0 + bcol);
        }
#pragma unroll
        for (int k = 0; k < 16; k++) {
            float ra[8], rb[8];
            *(float4*)(ra)     = *(const float4*)&As[buf][k][ty * 4];
            *(float4*)(ra + 4) = *(const float4*)&As[buf][k][ty * 4 + 64];
            *(float4*)(rb)     = *(const float4*)&Bs[buf][k][tx * 4];
            *(float4*)(rb + 4) = *(const float4*)&Bs[buf][k][tx * 4 + 64];
#pragma unroll
            for (int i = 0; i < 8; i++)
#pragma unroll
                for (int j = 0; j < 8; j++) acc[i][j] += ra[i] * rb[j];
        }
        if (t + 1 < kt_per_split) {
            const int nb = buf ^ 1;
            As[nb][acol + 0][arow] = a0.x; As[nb][acol + 1][arow] = a0.y;
            As[nb][acol + 2][arow] = a0.z; As[nb][acol + 3][arow] = a0.w;
            As[nb][acol + 0][arow + 64] = a1.x; As[nb][acol + 1][arow + 64] = a1.y;
            As[nb][acol + 2][arow + 64] = a1.z; As[nb][acol + 3][arow + 64] = a1.w;
            *(float4*)&Bs[nb][brow][bcol] = b0;
            *(float4*)&Bs[nb][brow + 8][bcol] = b1;
        }
        __syncthreads();
    }
#pragma unroll
    for (int i = 0; i < 8; i++) {
        const int r = m0 + (ty << 2) + (i & 3) + ((i >> 2) << 6);
        float* o = g_h2 + (size_t)r * PN2 + n0 + (tx << 2);
        atomicAdd(o + 0, acc[i][0]);
        atomicAdd(o + 1, acc[i][1]);
        atomicAdd(o + 2, acc[i][2]);
        atomicAdd(o + 3, acc[i][3]);
        atomicAdd(o + 64, acc[i][4]);
        atomicAdd(o + 65, acc[i][5]);
        atomicAdd(o + 66, acc[i][6]);
        atomicAdd(o + 67, acc[i][7]);
    }
}

// out2 = log_softmax(relu(h2 + bias)), one block per row
__global__ __launch_bounds__(256) void epilogue2_kernel(const float* __restrict__ bias,
                                                        float* __restrict__ out2) {
    const int row = blockIdx.x, tid = threadIdx.x;
    __shared__ float sred[8];
    __shared__ float sbcast;
    float4 v = *(const float4*)(g_h2 + (size_t)row * PN2 + tid * 4);
    float4 b = *(const float4*)(bias + tid * 4);
    v.x = fmaxf(v.x + b.x, 0.0f);
    v.y = fmaxf(v.y + b.y, 0.0f);
    v.z = fmaxf(v.z + b.z, 0.0f);
    v.w = fmaxf(v.w + b.w, 0.0f);
    float m = fmaxf(fmaxf(v.x, v.y), fmaxf(v.z, v.w));
#pragma unroll
    for (int o = 16; o; o >>= 1) m = fmaxf(m, __shfl_xor_sync(0xffffffffu, m, o));
    if ((tid & 31) == 0) sred[tid >> 5] = m;
    __syncthreads();
    if (tid == 0) {
        float t = sred[0];
#pragma unroll
        for (int i = 1; i < 8; i++) t = fmaxf(t, sred[i]);
        sbcast = t;
    }
    __syncthreads();
    m = sbcast;
    float s = __expf(v.x - m) + __expf(v.y - m) + __expf(v.z - m) + __expf(v.w - m);
#pragma unroll
    for (int o = 16; o; o >>= 1) s += __shfl_xor_sync(0xffffffffu, s, o);
    __syncthreads();
    if ((tid & 31) == 0) sred[tid >> 5] = s;
    __syncthreads();
    if (tid == 0) {
        float t = 0.0f;
#pragma unroll
        for (int i = 0; i < 8; i++) t += sred[i];
        sbcast = m + __logf(t);
    }
    __syncthreads();
    const float lse = sbcast;
    *(float4*)(out2 + (size_t)row * PN2 + tid * 4) =
        make_float4(v.x - lse, v.y - lse, v.z - lse, v.w - lse);
}

// =====================================================================
// launch — kernel launches ONLY
// =====================================================================
extern "C" void kernel_launch(void* const* d_in, const int* in_sizes, int n_in,
                              void* d_out, int out_size) {
    (void)in_sizes; (void)n_in; (void)out_size;
    const float* x_g1      = (const float*)d_in[0];
    const float* W_stc     = (const float*)d_in[1];
    const float* b_stc     = (const float*)d_in[2];
    const float* x_g2      = (const float*)d_in[3];
    const float* basis     = (const float*)d_in[4];
    const float* att       = (const float*)d_in[5];
    const float* root      = (const float*)d_in[6];
    const float* bias_rgcn = (const float*)d_in[7];
    const void*  ei1       = d_in[8];
    const void*  ei2       = d_in[9];
    const void*  et2       = d_in[10];
    float* out1 = (float*)d_out;
    float* out2 = out1 + (size_t)PN1 * PD;

    probe_kernel<<<1, 256>>>((const int*)ei1);
    zero_main_kernel<<<12500, 256>>>();   // 3.2M float4 slots

    // ---- Part 1 ----
    scatter1_kernel<<<PE1 / 8, 256>>>(x_g1, ei1);
    linear1_kernel<<<(PN1 + 63) / 64, 256>>>(W_stc, b_stc, out1);

    // ---- Part 2 ----
    deg2_kernel<<<(PE2 + 255) / 256, 256>>>(ei2);
    // h2 += x_g2 @ root (split-K=2)
    gemm_acc_kernel<<<dim3(8, 8, ZS_R), 256>>>(x_g2, root, KT_R);
    // 5 groups of 6 bases
    for (int g = 0; g < NGRP; g++) {
        zero_A_kernel<<<6144, 256>>>();
        build_A_kernel<<<(PE2 + 255) / 256, 256>>>(ei2, et2, att, g);
        gemm1_kernel<<<dim3(8, 8, GRP), 256>>>(x_g2);
        gemm_acc_kernel<<<dim3(8, 8, ZS_G), 256>>>(
            nullptr, basis + (size_t)g * GRP * PN2 * PN2, KT_G);
    }
    epilogue2_kernel<<<PN2, 256>>>(bias_rgcn, out2);
}

// round 11
// speedup vs baseline: 1.9535x; 1.9535x over previous
#include <cuda_runtime.h>
#include <cstdint>

// ---------------- problem dimensions ----------------
#define PN1 100000
#define PE1 1600000
#define PD  128
#define PN2 1024
#define PE2 200000
#define PNB 30
#define NKT_ACC 1984          // (30*1024 + 1024) / 16
#define ZS_ACC 8
#define KT_ACC (NKT_ACC / ZS_ACC)   // 248

// ---------------- device scratch ----------------
__device__ __align__(16) float g_deg1[PN1];
__device__ __align__(16) float g_agg1[(size_t)PN1 * PD];
__device__ __align__(16) float g_deg2[PN2];
__device__ __align__(16) float g_A[(size_t)PNB * PN2 * PN2];
__device__ __align__(16) float g_S[(size_t)PNB * PN2 * PN2];
__device__ __align__(16) float g_h2[(size_t)PN2 * PN2];
__device__ __align__(16) float g_Xt[(size_t)PN2 * PN2];
__device__ __align__(16) float g_Bt[(size_t)(PNB + 1) * PN2 * PN2];
__device__ int g_is64;

// ---------------- helpers ----------------
__device__ __forceinline__ int load_idx(const void* p, size_t idx) {
    if (g_is64) return (int)((const long long*)p)[idx];
    return ((const int*)p)[idx];
}

__device__ __forceinline__ uint32_t smem_u32(const void* p) {
    uint32_t r;
    asm("{ .reg .u64 t; cvta.to.shared.u64 t, %1; cvt.u32.u64 %0, t; }"
        : "=r"(r) : "l"(p));
    return r;
}

__device__ __forceinline__ void ldsm4(uint32_t& r0, uint32_t& r1, uint32_t& r2,
                                      uint32_t& r3, uint32_t addr) {
    asm volatile("ldmatrix.sync.aligned.m8n8.x4.shared.b16 {%0,%1,%2,%3}, [%4];"
                 : "=r"(r0), "=r"(r1), "=r"(r2), "=r"(r3) : "r"(addr));
}

__device__ __forceinline__ void mma_tf32(float* c, const uint32_t* a,
                                         uint32_t b0, uint32_t b1) {
    asm volatile(
        "mma.sync.aligned.m16n8k8.row.col.f32.tf32.tf32.f32 "
        "{%0,%1,%2,%3},{%4,%5,%6,%7},{%8,%9},{%0,%1,%2,%3};"
        : "+f"(c[0]), "+f"(c[1]), "+f"(c[2]), "+f"(c[3])
        : "r"(a[0]), "r"(a[1]), "r"(a[2]), "r"(a[3]), "r"(b0), "r"(b1));
}

// tf32 compute core: 128x128 block, 8 warps, warp tile 32x64, BK=16.
// Smem rows are padded to 20 floats; ldmatrix b16 on fp32 data: one 8x8 b16
// matrix == 8x4 fp32 tile with thread map (lane>>2, lane&3) — exactly the
// tf32 mma A/B fragment quadrant layout.
__device__ __forceinline__ void gemm_compute_tile(uint32_t AsU, uint32_t BsU,
                                                  int base_a, int base_b,
                                                  float (&acc)[2][8][4]) {
    uint32_t a[2][2][4], b[8][4];
#pragma unroll
    for (int mt = 0; mt < 2; mt++)
#pragma unroll
        for (int ks = 0; ks < 2; ks++)
            ldsm4(a[mt][ks][0], a[mt][ks][1], a[mt][ks][2], a[mt][ks][3],
                  AsU + base_a + mt * 1280 + ks * 32);
#pragma unroll
    for (int nt = 0; nt < 8; nt++)
        ldsm4(b[nt][0], b[nt][1], b[nt][2], b[nt][3], BsU + base_b + nt * 640);
#pragma unroll
    for (int mt = 0; mt < 2; mt++)
#pragma unroll
        for (int nt = 0; nt < 8; nt++) {
            mma_tf32(acc[mt][nt], a[mt][0], b[nt][0], b[nt][1]);
            mma_tf32(acc[mt][nt], a[mt][1], b[nt][2], b[nt][3]);
        }
}

// =====================================================================
// probe / zero / transposes
// =====================================================================
__global__ void probe_kernel(const int* __restrict__ ei_words) {
    __shared__ int found;
    if (threadIdx.x == 0) found = 0;
    __syncthreads();
    for (int i = threadIdx.x; i < 4096; i += 256)
        if (ei_words[2 * i + 1] != 0) found = 1;
    __syncthreads();
    if (threadIdx.x == 0) g_is64 = found ? 0 : 1;
}

__global__ void zero_main_kernel() {
    const size_t i = (size_t)blockIdx.x * blockDim.x + threadIdx.x;
    const float4 z = make_float4(0.f, 0.f, 0.f, 0.f);
    if (i < (size_t)PN1 * PD / 4)  ((float4*)g_agg1)[i] = z;
    if (i < PN1 / 4)               ((float4*)g_deg1)[i] = z;
    if (i < (size_t)PN2 * PN2 / 4) ((float4*)g_h2)[i] = z;
    if (i < PN2 / 4)               ((float4*)g_deg2)[i] = z;
}

__global__ void zero_A_kernel() {
    const size_t i = (size_t)blockIdx.x * blockDim.x + threadIdx.x;
    if (i < (size_t)PNB * PN2 * PN2 / 4)
        ((float4*)g_A)[i] = make_float4(0.f, 0.f, 0.f, 0.f);
}

__device__ __forceinline__ void transpose_core(float* dst,
                                               const float* __restrict__ src) {
    __shared__ float tile[32][33];
    int c = blockIdx.x * 32 + threadIdx.x;
    int r = blockIdx.y * 32 + threadIdx.y;
#pragma unroll
    for (int i = 0; i < 32; i += 8)
        tile[threadIdx.y + i][threadIdx.x] = src[(size_t)(r + i) * PN2 + c];
    __syncthreads();
    c = blockIdx.y * 32 + threadIdx.x;
    r = blockIdx.x * 32 + threadIdx.y;
#pragma unroll
    for (int i = 0; i < 32; i += 8)
        dst[(size_t)(r + i) * PN2 + c] = tile[threadIdx.x][threadIdx.y + i];
}

__global__ void transpose_basis_kernel(const float* __restrict__ src) {
    const size_t zoff = (size_t)blockIdx.z << 20;
    transpose_core(g_Bt + zoff, src + zoff);
}
__global__ void transpose_root_kernel(const float* __restrict__ src) {
    transpose_core(g_Bt + ((size_t)PNB << 20), src);
}
__global__ void transpose_x_kernel(const float* __restrict__ src) {
    transpose_core(g_Xt, src);
}

// =====================================================================
// Part 1: STCConv
// =====================================================================
__global__ void scatter1_kernel(const float* __restrict__ x,
                                const void* __restrict__ ei) {
    const unsigned gw = (blockIdx.x * blockDim.x + threadIdx.x) >> 5;
    const int lane = threadIdx.x & 31;
    if (gw >= PE1) return;
    const int s = load_idx(ei, gw);
    const int d = load_idx(ei, (size_t)PE1 + gw);
    float4 v = *(const float4*)(x + (size_t)s * PD + lane * 4);
    float* a = g_agg1 + (size_t)d * PD + lane * 4;
    asm volatile("red.global.add.v4.f32 [%0], {%1,%2,%3,%4};"
                 :: "l"(a), "f"(v.x), "f"(v.y), "f"(v.z), "f"(v.w) : "memory");
    if (lane == 0) atomicAdd(&g_deg1[d], 1.0f);
}

__global__ __launch_bounds__(256) void linear1_kernel(const float* __restrict__ W,
                                                      const float* __restrict__ bias,
                                                      float* __restrict__ out1) {
    __shared__ float Ws[64 * 128];
    const int tid = threadIdx.x;
    const int lane = tid & 31;
    const int warp = tid >> 5;
    const int row0 = blockIdx.x * 64 + warp * 8;
    const int nrow = max(0, min(8, PN1 - row0));
    const float4 bv = *(const float4*)(bias + lane * 4);

    float acc[8][4];
#pragma unroll
    for (int r = 0; r < 8; r++) {
        acc[r][0] = bv.x; acc[r][1] = bv.y; acc[r][2] = bv.z; acc[r][3] = bv.w;
    }

#pragma unroll 1
    for (int half = 0; half < 2; half++) {
        __syncthreads();
        for (int i = tid; i < 2048; i += 256)
            ((float4*)Ws)[i] = ((const float4*)W)[half * 2048 + i];
        __syncthreads();
        for (int r = 0; r < nrow; r++) {
            const int row = row0 + r;
            const float invd = 1.0f / fmaxf(g_deg1[row], 1.0f);
            float4 v = *(const float4*)(g_agg1 + (size_t)row * PD +
                                        half * 64 + (lane & 15) * 4);
            v.x *= invd; v.y *= invd; v.z *= invd; v.w *= invd;
#pragma unroll
            for (int k4 = 0; k4 < 16; k4++) {
                float r0 = __shfl_sync(0xffffffffu, v.x, k4);
                float r1 = __shfl_sync(0xffffffffu, v.y, k4);
                float r2 = __shfl_sync(0xffffffffu, v.z, k4);
                float r3 = __shfl_sync(0xffffffffu, v.w, k4);
                const float* wp = Ws + (k4 * 4) * PD + lane * 4;
                float4 w0 = *(const float4*)(wp);
                float4 w1 = *(const float4*)(wp + PD);
                float4 w2 = *(const float4*)(wp + 2 * PD);
                float4 w3 = *(const float4*)(wp + 3 * PD);
                acc[r][0] += r0 * w0.x + r1 * w1.x + r2 * w2.x + r3 * w3.x;
                acc[r][1] += r0 * w0.y + r1 * w1.y + r2 * w2.y + r3 * w3.y;
                acc[r][2] += r0 * w0.z + r1 * w1.z + r2 * w2.z + r3 * w3.z;
                acc[r][3] += r0 * w0.w + r1 * w1.w + r2 * w2.w + r3 * w3.w;
            }
        }
    }

    for (int r = 0; r < nrow; r++) {
        float a0 = fmaxf(acc[r][0], 0.0f), a1 = fmaxf(acc[r][1], 0.0f);
        float a2 = fmaxf(acc[r][2], 0.0f), a3 = fmaxf(acc[r][3], 0.0f);
        float m = fmaxf(fmaxf(a0, a1), fmaxf(a2, a3));
#pragma unroll
        for (int o = 16; o; o >>= 1) m = fmaxf(m, __shfl_xor_sync(0xffffffffu, m, o));
        float s = __expf(a0 - m) + __expf(a1 - m) + __expf(a2 - m) + __expf(a3 - m);
#pragma unroll
        for (int o = 16; o; o >>= 1) s += __shfl_xor_sync(0xffffffffu, s, o);
        float lse = m + __logf(s);
        *(float4*)(out1 + (size_t)(row0 + r) * PD + lane * 4) =
            make_float4(a0 - lse, a1 - lse, a2 - lse, a3 - lse);
    }
}

// =====================================================================
// Part 2: densified RGCN
// =====================================================================
__global__ void deg2_kernel(const void* __restrict__ ei) {
    int e = blockIdx.x * blockDim.x + threadIdx.x;
    if (e < PE2) atomicAdd(&g_deg2[load_idx(ei, (size_t)PE2 + e)], 1.0f);
}

__global__ void build_A_kernel(const void* __restrict__ ei,
                               const void* __restrict__ et,
                               const float* __restrict__ att) {
    int e = blockIdx.x * blockDim.x + threadIdx.x;
    if (e >= PE2) return;
    const int s = load_idx(ei, e);
    const int d = load_idx(ei, (size_t)PE2 + e);
    const int t = load_idx(et, e);
    const float w = 1.0f / fmaxf(g_deg2[d], 1.0f);
    const float* ar = att + (size_t)t * PNB;
    float* base = g_A + (size_t)d * PN2 + s;
#pragma unroll
    for (int b = 0; b < PNB; b++)
        atomicAdd(base + ((size_t)b << 20), ar[b] * w);
}

// tf32 batched GEMM: S[z] = A[z] @ X   (B operand from g_Xt, pre-transposed)
__global__ __launch_bounds__(256, 1) void gemm1_tf32() {
    const int z = blockIdx.z;
    const float* A = g_A + ((size_t)z << 20);
    float* C = g_S + ((size_t)z << 20);
    const int m0 = blockIdx.y * 128, n0 = blockIdx.x * 128;
    __shared__ float As[2 * 2560];
    __shared__ float Bs[2 * 2560];
    const int tid = threadIdx.x, lane = tid & 31, warp = tid >> 5;
    const int wm = (warp >> 1) * 32, wn = (warp & 1) * 64;
    const int mlo = tid >> 2, q4 = (tid & 3) * 4;
    const int s0 = mlo * 20 + q4, s1 = (mlo + 64) * 20 + q4;
    const float* ap0 = A + (size_t)(m0 + mlo) * PN2 + q4;
    const float* ap1 = ap0 + (size_t)64 * PN2;
    const float* bp0 = g_Xt + (size_t)(n0 + mlo) * PN2 + q4;
    const float* bp1 = bp0 + (size_t)64 * PN2;
    const uint32_t AsU = smem_u32(As), BsU = smem_u32(Bs);
    const int base_a = ((wm + (lane & 15)) * 20 + (lane >> 4) * 4) * 4;
    const int base_b = ((wn + (lane & 7)) * 20 + (lane >> 3) * 4) * 4;

    float acc[2][8][4];
#pragma unroll
    for (int i = 0; i < 2; i++)
#pragma unroll
        for (int j = 0; j < 8; j++)
#pragma unroll
            for (int k = 0; k < 4; k++) acc[i][j][k] = 0.0f;

    float4 pa0 = *(const float4*)ap0, pa1 = *(const float4*)ap1;
    float4 pb0 = *(const float4*)bp0, pb1 = *(const float4*)bp1;
    *(float4*)&As[s0] = pa0; *(float4*)&As[s1] = pa1;
    *(float4*)&Bs[s0] = pb0; *(float4*)&Bs[s1] = pb1;
    __syncthreads();

    const int NT = PN2 / 16;   // 64
    for (int t = 0; t < NT; t++) {
        const int cur = t & 1;
        if (t + 1 < NT) {
            pa0 = *(const float4*)(ap0 + (t + 1) * 16);
            pa1 = *(const float4*)(ap1 + (t + 1) * 16);
            pb0 = *(const float4*)(bp0 + (t + 1) * 16);
            pb1 = *(const float4*)(bp1 + (t + 1) * 16);
        }
        gemm_compute_tile(AsU + cur * 10240, BsU + cur * 10240, base_a, base_b, acc);
        if (t + 1 < NT) {
            const int nx = (cur ^ 1) * 2560;
            *(float4*)&As[nx + s0] = pa0; *(float4*)&As[nx + s1] = pa1;
            *(float4*)&Bs[nx + s0] = pb0; *(float4*)&Bs[nx + s1] = pb1;
        }
        __syncthreads();
    }
#pragma unroll
    for (int mt = 0; mt < 2; mt++)
#pragma unroll
        for (int nt = 0; nt < 8; nt++) {
            const int r = m0 + wm + mt * 16 + (lane >> 2);
            const int c = n0 + wn + nt * 8 + (lane & 3) * 2;
            *(float2*)&C[(size_t)r * PN2 + c] =
                make_float2(acc[mt][nt][0], acc[mt][nt][1]);
            *(float2*)&C[(size_t)(r + 8) * PN2 + c] =
                make_float2(acc[mt][nt][2], acc[mt][nt][3]);
        }
}

// tf32 split-K GEMM: h2 += [S | x_g2] @ [basis ; root]  (B from g_Bt)
__global__ __launch_bounds__(256, 1) void gemm_acc_tf32(const float* __restrict__ xg2) {
    const int m0 = blockIdx.y * 128, n0 = blockIdx.x * 128;
    const int kt0 = blockIdx.z * KT_ACC;
    __shared__ float As[2 * 2560];
    __shared__ float Bs[2 * 2560];
    const int tid = threadIdx.x, lane = tid & 31, warp = tid >> 5;
    const int wm = (warp >> 1) * 32, wn = (warp & 1) * 64;
    const int mlo = tid >> 2, q4 = (tid & 3) * 4;
    const int s0 = mlo * 20 + q4, s1 = (mlo + 64) * 20 + q4;
    const uint32_t AsU = smem_u32(As), BsU = smem_u32(Bs);
    const int base_a = ((wm + (lane & 15)) * 20 + (lane >> 4) * 4) * 4;
    const int base_b = ((wn + (lane & 7)) * 20 + (lane >> 3) * 4) * 4;

    auto loadA = [&](int kt, float4& r0, float4& r1) {
        const float* Ab; int ko;
        if (kt < PNB * 64) { Ab = g_S + ((size_t)(kt >> 6) << 20); ko = (kt & 63) << 4; }
        else               { Ab = xg2; ko = (kt - PNB * 64) << 4; }
        const float* p = Ab + (size_t)(m0 + mlo) * PN2 + ko + q4;
        r0 = *(const float4*)p;
        r1 = *(const float4*)(p + (size_t)64 * PN2);
    };
    auto loadB = [&](int kt, float4& r0, float4& r1) {
        const float* p = g_Bt + ((size_t)(kt >> 6) << 20) +
                         (size_t)(n0 + mlo) * PN2 + ((kt & 63) << 4) + q4;
        r0 = *(const float4*)p;
        r1 = *(const float4*)(p + (size_t)64 * PN2);
    };

    float acc[2][8][4];
#pragma unroll
    for (int i = 0; i < 2; i++)
#pragma unroll
        for (int j = 0; j < 8; j++)
#pragma unroll
            for (int k = 0; k < 4; k++) acc[i][j][k] = 0.0f;

    float4 pa0, pa1, pb0, pb1;
    loadA(kt0, pa0, pa1);
    loadB(kt0, pb0, pb1);
    *(float4*)&As[s0] = pa0; *(float4*)&As[s1] = pa1;
    *(float4*)&Bs[s0] = pb0; *(float4*)&Bs[s1] = pb1;
    __syncthreads();

    for (int t = 0; t < KT_ACC; t++) {
        const int cur = t & 1;
        if (t + 1 < KT_ACC) {
            loadA(kt0 + t + 1, pa0, pa1);
            loadB(kt0 + t + 1, pb0, pb1);
        }
        gemm_compute_tile(AsU + cur * 10240, BsU + cur * 10240, base_a, base_b, acc);
        if (t + 1 < KT_ACC) {
            const int nx = (cur ^ 1) * 2560;
            *(float4*)&As[nx + s0] = pa0; *(float4*)&As[nx + s1] = pa1;
            *(float4*)&Bs[nx + s0] = pb0; *(float4*)&Bs[nx + s1] = pb1;
        }
        __syncthreads();
    }
#pragma unroll
    for (int mt = 0; mt < 2; mt++)
#pragma unroll
        for (int nt = 0; nt < 8; nt++) {
            const int r = m0 + wm + mt * 16 + (lane >> 2);
            const int c = n0 + wn + nt * 8 + (lane & 3) * 2;
            atomicAdd(&g_h2[(size_t)r * PN2 + c],           acc[mt][nt][0]);
            atomicAdd(&g_h2[(size_t)r * PN2 + c + 1],       acc[mt][nt][1]);
            atomicAdd(&g_h2[(size_t)(r + 8) * PN2 + c],     acc[mt][nt][2]);
            atomicAdd(&g_h2[(size_t)(r + 8) * PN2 + c + 1], acc[mt][nt][3]);
        }
}

// out2 = log_softmax(relu(h2 + bias)), one block per row
__global__ __launch_bounds__(256) void epilogue2_kernel(const float* __restrict__ bias,
                                                        float* __restrict__ out2) {
    const int row = blockIdx.x, tid = threadIdx.x;
    __shared__ float sred[8];
    __shared__ float sbcast;
    float4 v = *(const float4*)(g_h2 + (size_t)row * PN2 + tid * 4);
    float4 b = *(const float4*)(bias + tid * 4);
    v.x = fmaxf(v.x + b.x, 0.0f);
    v.y = fmaxf(v.y + b.y, 0.0f);
    v.z = fmaxf(v.z + b.z, 0.0f);
    v.w = fmaxf(v.w + b.w, 0.0f);
    float m = fmaxf(fmaxf(v.x, v.y), fmaxf(v.z, v.w));
#pragma unroll
    for (int o = 16; o; o >>= 1) m = fmaxf(m, __shfl_xor_sync(0xffffffffu, m, o));
    if ((tid & 31) == 0) sred[tid >> 5] = m;
    __syncthreads();
    if (tid == 0) {
        float t = sred[0];
#pragma unroll
        for (int i = 1; i < 8; i++) t = fmaxf(t, sred[i]);
        sbcast = t;
    }
    __syncthreads();
    m = sbcast;
    float s = __expf(v.x - m) + __expf(v.y - m) + __expf(v.z - m) + __expf(v.w - m);
#pragma unroll
    for (int o = 16; o; o >>= 1) s += __shfl_xor_sync(0xffffffffu, s, o);
    __syncthreads();
    if ((tid & 31) == 0) sred[tid >> 5] = s;
    __syncthreads();
    if (tid == 0) {
        float t = 0.0f;
#pragma unroll
        for (int i = 0; i < 8; i++) t += sred[i];
        sbcast = m + __logf(t);
    }
    __syncthreads();
    const float lse = sbcast;
    *(float4*)(out2 + (size_t)row * PN2 + tid * 4) =
        make_float4(v.x - lse, v.y - lse, v.z - lse, v.w - lse);
}

// =====================================================================
// launch — kernel launches ONLY
// =====================================================================
extern "C" void kernel_launch(void* const* d_in, const int* in_sizes, int n_in,
                              void* d_out, int out_size) {
    (void)in_sizes; (void)n_in; (void)out_size;
    const float* x_g1      = (const float*)d_in[0];
    const float* W_stc     = (const float*)d_in[1];
    const float* b_stc     = (const float*)d_in[2];
    const float* x_g2      = (const float*)d_in[3];
    const float* basis     = (const float*)d_in[4];
    const float* att       = (const float*)d_in[5];
    const float* root      = (const float*)d_in[6];
    const float* bias_rgcn = (const float*)d_in[7];
    const void*  ei1       = d_in[8];
    const void*  ei2       = d_in[9];
    const void*  et2       = d_in[10];
    float* out1 = (float*)d_out;
    float* out2 = out1 + (size_t)PN1 * PD;

    probe_kernel<<<1, 256>>>((const int*)ei1);
    zero_main_kernel<<<12500, 256>>>();
    zero_A_kernel<<<30720, 256>>>();

    // pre-transpose tf32 B operands
    {
        dim3 blk(32, 8);
        transpose_basis_kernel<<<dim3(32, 32, PNB), blk>>>(basis);
        transpose_root_kernel<<<dim3(32, 32), blk>>>(root);
        transpose_x_kernel<<<dim3(32, 32), blk>>>(x_g2);
    }

    // ---- Part 1 ----
    scatter1_kernel<<<PE1 / 8, 256>>>(x_g1, ei1);
    linear1_kernel<<<(PN1 + 63) / 64, 256>>>(W_stc, b_stc, out1);

    // ---- Part 2 ----
    deg2_kernel<<<(PE2 + 255) / 256, 256>>>(ei2);
    build_A_kernel<<<(PE2 + 255) / 256, 256>>>(ei2, et2, att);
    gemm1_tf32<<<dim3(8, 8, PNB), 256>>>();
    gemm_acc_tf32<<<dim3(8, 8, ZS_ACC), 256>>>(x_g2);
    epilogue2_kernel<<<PN2, 256>>>(bias_rgcn, out2);
}

// round 12
// speedup vs baseline: 2.6549x; 1.3590x over previous
#include <cuda_runtime.h>
#include <cstdint>

// ---------------- problem dimensions ----------------
#define PN1 100000
#define PE1 1600000
#define PD  128
#define PN2 1024
#define PE2 200000
#define PNB 30
#define NKT_ACC 1984          // (30*1024 + 1024) / 16
#define ZS_ACC 8
#define KT_ACC (NKT_ACC / ZS_ACC)   // 248

// ---------------- device scratch ----------------
__device__ __align__(16) float g_deg1[PN1];
__device__ __align__(16) float g_agg1[(size_t)PN1 * PD];
__device__ __align__(16) float g_deg2[PN2];
__device__ __align__(16) float g_A[(size_t)PNB * PN2 * PN2];
__device__ __align__(16) float g_S[(size_t)PNB * PN2 * PN2];
__device__ __align__(16) float g_h2[(size_t)PN2 * PN2];
__device__ __align__(16) float g_Xt[(size_t)PN2 * PN2];
__device__ __align__(16) float g_Bt[(size_t)(PNB + 1) * PN2 * PN2];
__device__ int g_is64;

// ---------------- helpers ----------------
__device__ __forceinline__ int load_idx(const void* p, size_t idx) {
    if (g_is64) return (int)((const long long*)p)[idx];
    return ((const int*)p)[idx];
}

__device__ __forceinline__ uint32_t smem_u32(const void* p) {
    uint32_t r;
    asm("{ .reg .u64 t; cvta.to.shared.u64 t, %1; cvt.u32.u64 %0, t; }"
        : "=r"(r) : "l"(p));
    return r;
}

__device__ __forceinline__ void ldsm4(uint32_t& r0, uint32_t& r1, uint32_t& r2,
                                      uint32_t& r3, uint32_t addr) {
    asm volatile("ldmatrix.sync.aligned.m8n8.x4.shared.b16 {%0,%1,%2,%3}, [%4];"
                 : "=r"(r0), "=r"(r1), "=r"(r2), "=r"(r3) : "r"(addr));
}

__device__ __forceinline__ void mma_tf32(float* c, const uint32_t* a,
                                         uint32_t b0, uint32_t b1) {
    asm volatile(
        "mma.sync.aligned.m16n8k8.row.col.f32.tf32.tf32.f32 "
        "{%0,%1,%2,%3},{%4,%5,%6,%7},{%8,%9},{%0,%1,%2,%3};"
        : "+f"(c[0]), "+f"(c[1]), "+f"(c[2]), "+f"(c[3])
        : "r"(a[0]), "r"(a[1]), "r"(a[2]), "r"(a[3]), "r"(b0), "r"(b1));
}

__device__ __forceinline__ void cp16(uint32_t s, const void* g) {
    asm volatile("cp.async.cg.shared.global [%0], [%1], 16;" :: "r"(s), "l"(g));
}
#define CP_COMMIT() asm volatile("cp.async.commit_group;")
#define CP_WAIT1()  asm volatile("cp.async.wait_group 1;")
#define CP_WAIT0()  asm volatile("cp.async.wait_group 0;")

// tf32 compute core: 128x128 block, 8 warps, warp tile 32x64, BK=16.
// Smem rows padded to 20 floats (conflict-free ldmatrix). B-fragments use a
// single reusable 4-reg buffer to stay under 128 regs (2 CTAs/SM).
__device__ __forceinline__ void gemm_compute_tile(uint32_t AsU, uint32_t BsU,
                                                  int base_a, int base_b,
                                                  float (&acc)[2][8][4]) {
    uint32_t a[2][2][4];
#pragma unroll
    for (int mt = 0; mt < 2; mt++)
#pragma unroll
        for (int ks = 0; ks < 2; ks++)
            ldsm4(a[mt][ks][0], a[mt][ks][1], a[mt][ks][2], a[mt][ks][3],
                  AsU + base_a + mt * 1280 + ks * 32);
#pragma unroll
    for (int nt = 0; nt < 8; nt++) {
        uint32_t b[4];
        ldsm4(b[0], b[1], b[2], b[3], BsU + base_b + nt * 640);
        mma_tf32(acc[0][nt], a[0][0], b[0], b[1]);
        mma_tf32(acc[0][nt], a[0][1], b[2], b[3]);
        mma_tf32(acc[1][nt], a[1][0], b[0], b[1]);
        mma_tf32(acc[1][nt], a[1][1], b[2], b[3]);
    }
}

// =====================================================================
// probe / zero / transposes
// =====================================================================
__global__ void probe_kernel(const int* __restrict__ ei_words) {
    __shared__ int found;
    if (threadIdx.x == 0) found = 0;
    __syncthreads();
    for (int i = threadIdx.x; i < 4096; i += 256)
        if (ei_words[2 * i + 1] != 0) found = 1;
    __syncthreads();
    if (threadIdx.x == 0) g_is64 = found ? 0 : 1;
}

__global__ void zero_main_kernel() {
    const size_t i = (size_t)blockIdx.x * blockDim.x + threadIdx.x;
    const float4 z = make_float4(0.f, 0.f, 0.f, 0.f);
    if (i < (size_t)PN1 * PD / 4)  ((float4*)g_agg1)[i] = z;
    if (i < PN1 / 4)               ((float4*)g_deg1)[i] = z;
    if (i < (size_t)PN2 * PN2 / 4) ((float4*)g_h2)[i] = z;
    if (i < PN2 / 4)               ((float4*)g_deg2)[i] = z;
}

__global__ void zero_A_kernel() {
    const size_t i = (size_t)blockIdx.x * blockDim.x + threadIdx.x;
    if (i < (size_t)PNB * PN2 * PN2 / 4)
        ((float4*)g_A)[i] = make_float4(0.f, 0.f, 0.f, 0.f);
}

__device__ __forceinline__ void transpose_core(float* dst,
                                               const float* __restrict__ src) {
    __shared__ float tile[32][33];
    int c = blockIdx.x * 32 + threadIdx.x;
    int r = blockIdx.y * 32 + threadIdx.y;
#pragma unroll
    for (int i = 0; i < 32; i += 8)
        tile[threadIdx.y + i][threadIdx.x] = src[(size_t)(r + i) * PN2 + c];
    __syncthreads();
    c = blockIdx.y * 32 + threadIdx.x;
    r = blockIdx.x * 32 + threadIdx.y;
#pragma unroll
    for (int i = 0; i < 32; i += 8)
        dst[(size_t)(r + i) * PN2 + c] = tile[threadIdx.x][threadIdx.y + i];
}

__global__ void transpose_basis_kernel(const float* __restrict__ src) {
    const size_t zoff = (size_t)blockIdx.z << 20;
    transpose_core(g_Bt + zoff, src + zoff);
}
__global__ void transpose_root_kernel(const float* __restrict__ src) {
    transpose_core(g_Bt + ((size_t)PNB << 20), src);
}
__global__ void transpose_x_kernel(const float* __restrict__ src) {
    transpose_core(g_Xt, src);
}

// =====================================================================
// Part 1: STCConv
// =====================================================================
__global__ void scatter1_kernel(const float* __restrict__ x,
                                const void* __restrict__ ei) {
    const unsigned gw = (blockIdx.x * blockDim.x + threadIdx.x) >> 5;
    const int lane = threadIdx.x & 31;
    if (gw >= PE1) return;
    const int s = load_idx(ei, gw);
    const int d = load_idx(ei, (size_t)PE1 + gw);
    float4 v = *(const float4*)(x + (size_t)s * PD + lane * 4);
    float* a = g_agg1 + (size_t)d * PD + lane * 4;
    asm volatile("red.global.add.v4.f32 [%0], {%1,%2,%3,%4};"
                 :: "l"(a), "f"(v.x), "f"(v.y), "f"(v.z), "f"(v.w) : "memory");
    if (lane == 0) atomicAdd(&g_deg1[d], 1.0f);
}

// fused linear + relu + log_softmax. W loads hoisted out of the row loop
// (they were repeated 8x and saturated L1).
__global__ __launch_bounds__(256) void linear1_kernel(const float* __restrict__ W,
                                                      const float* __restrict__ bias,
                                                      float* __restrict__ out1) {
    __shared__ float Ws[64 * 128];
    const int tid = threadIdx.x;
    const int lane = tid & 31;
    const int warp = tid >> 5;
    const int row0 = blockIdx.x * 64 + warp * 8;
    const int nrow = max(0, min(8, PN1 - row0));
    const float4 bv = *(const float4*)(bias + lane * 4);

    float acc[8][4];
#pragma unroll
    for (int r = 0; r < 8; r++) {
        acc[r][0] = bv.x; acc[r][1] = bv.y; acc[r][2] = bv.z; acc[r][3] = bv.w;
    }

#pragma unroll 1
    for (int half = 0; half < 2; half++) {
        __syncthreads();
        for (int i = tid; i < 2048; i += 256)
            ((float4*)Ws)[i] = ((const float4*)W)[half * 2048 + i];
        __syncthreads();

        float4 vr[8];
#pragma unroll
        for (int r = 0; r < 8; r++) {
            const int row = row0 + r;
            if (row < PN1) {
                const float invd = 1.0f / fmaxf(g_deg1[row], 1.0f);
                float4 v = *(const float4*)(g_agg1 + (size_t)row * PD +
                                            half * 64 + (lane & 15) * 4);
                vr[r] = make_float4(v.x * invd, v.y * invd, v.z * invd, v.w * invd);
            } else {
                vr[r] = make_float4(0.f, 0.f, 0.f, 0.f);
            }
        }
#pragma unroll
        for (int k4 = 0; k4 < 16; k4++) {
            const float* wp = Ws + (k4 * 4) * PD + lane * 4;
            float4 w0 = *(const float4*)(wp);
            float4 w1 = *(const float4*)(wp + PD);
            float4 w2 = *(const float4*)(wp + 2 * PD);
            float4 w3 = *(const float4*)(wp + 3 * PD);
#pragma unroll
            for (int r = 0; r < 8; r++) {
                float r0 = __shfl_sync(0xffffffffu, vr[r].x, k4);
                float r1 = __shfl_sync(0xffffffffu, vr[r].y, k4);
                float r2 = __shfl_sync(0xffffffffu, vr[r].z, k4);
                float r3 = __shfl_sync(0xffffffffu, vr[r].w, k4);
                acc[r][0] += r0 * w0.x + r1 * w1.x + r2 * w2.x + r3 * w3.x;
                acc[r][1] += r0 * w0.y + r1 * w1.y + r2 * w2.y + r3 * w3.y;
                acc[r][2] += r0 * w0.z + r1 * w1.z + r2 * w2.z + r3 * w3.z;
                acc[r][3] += r0 * w0.w + r1 * w1.w + r2 * w2.w + r3 * w3.w;
            }
        }
    }

    for (int r = 0; r < nrow; r++) {
        float a0 = fmaxf(acc[r][0], 0.0f), a1 = fmaxf(acc[r][1], 0.0f);
        float a2 = fmaxf(acc[r][2], 0.0f), a3 = fmaxf(acc[r][3], 0.0f);
        float m = fmaxf(fmaxf(a0, a1), fmaxf(a2, a3));
#pragma unroll
        for (int o = 16; o; o >>= 1) m = fmaxf(m, __shfl_xor_sync(0xffffffffu, m, o));
        float s = __expf(a0 - m) + __expf(a1 - m) + __expf(a2 - m) + __expf(a3 - m);
#pragma unroll
        for (int o = 16; o; o >>= 1) s += __shfl_xor_sync(0xffffffffu, s, o);
        float lse = m + __logf(s);
        *(float4*)(out1 + (size_t)(row0 + r) * PD + lane * 4) =
            make_float4(a0 - lse, a1 - lse, a2 - lse, a3 - lse);
    }
}

// =====================================================================
// Part 2: densified RGCN
// =====================================================================
__global__ void deg2_kernel(const void* __restrict__ ei) {
    int e = blockIdx.x * blockDim.x + threadIdx.x;
    if (e < PE2) atomicAdd(&g_deg2[load_idx(ei, (size_t)PE2 + e)], 1.0f);
}

__global__ void build_A_kernel(const void* __restrict__ ei,
                               const void* __restrict__ et,
                               const float* __restrict__ att) {
    int e = blockIdx.x * blockDim.x + threadIdx.x;
    if (e >= PE2) return;
    const int s = load_idx(ei, e);
    const int d = load_idx(ei, (size_t)PE2 + e);
    const int t = load_idx(et, e);
    const float w = 1.0f / fmaxf(g_deg2[d], 1.0f);
    const float* ar = att + (size_t)t * PNB;
    float* base = g_A + (size_t)d * PN2 + s;
#pragma unroll
    for (int b = 0; b < PNB; b++)
        atomicAdd(base + ((size_t)b << 20), ar[b] * w);
}

// tf32 batched GEMM: S[z] = A[z] @ X  (B from g_Xt). cp.async double buffer.
__global__ __launch_bounds__(256, 2) void gemm1_tf32() {
    const int z = blockIdx.z;
    const float* A = g_A + ((size_t)z << 20);
    float* C = g_S + ((size_t)z << 20);
    const int m0 = blockIdx.y * 128, n0 = blockIdx.x * 128;
    __shared__ float As[2 * 2560];
    __shared__ float Bs[2 * 2560];
    const int tid = threadIdx.x, lane = tid & 31, warp = tid >> 5;
    const int wm = (warp >> 1) * 32, wn = (warp & 1) * 64;
    const int mlo = tid >> 2, q4 = (tid & 3) * 4;
    const int s0 = (mlo * 20 + q4) * 4, s1 = ((mlo + 64) * 20 + q4) * 4;   // bytes
    const float* ap0 = A + (size_t)(m0 + mlo) * PN2 + q4;
    const float* ap1 = ap0 + (size_t)64 * PN2;
    const float* bp0 = g_Xt + (size_t)(n0 + mlo) * PN2 + q4;
    const float* bp1 = bp0 + (size_t)64 * PN2;
    const uint32_t AsU = smem_u32(As), BsU = smem_u32(Bs);
    const int base_a = ((wm + (lane & 15)) * 20 + (lane >> 4) * 4) * 4;
    const int base_b = ((wn + (lane & 7)) * 20 + (lane >> 3) * 4) * 4;

    float acc[2][8][4];
#pragma unroll
    for (int i = 0; i < 2; i++)
#pragma unroll
        for (int j = 0; j < 8; j++)
#pragma unroll
            for (int k = 0; k < 4; k++) acc[i][j][k] = 0.0f;

    cp16(AsU + s0, ap0); cp16(AsU + s1, ap1);
    cp16(BsU + s0, bp0); cp16(BsU + s1, bp1);
    CP_COMMIT();

    const int NT = PN2 / 16;   // 64
    for (int t = 0; t < NT; t++) {
        if (t + 1 < NT) {
            const int nx = ((t + 1) & 1) * 10240;
            const int ko = (t + 1) * 16;
            cp16(AsU + nx + s0, ap0 + ko); cp16(AsU + nx + s1, ap1 + ko);
            cp16(BsU + nx + s0, bp0 + ko); cp16(BsU + nx + s1, bp1 + ko);
            CP_COMMIT();
            CP_WAIT1();
        } else {
            CP_WAIT0();
        }
        __syncthreads();
        const int cur = (t & 1) * 10240;
        gemm_compute_tile(AsU + cur, BsU + cur, base_a, base_b, acc);
        __syncthreads();
    }
#pragma unroll
    for (int mt = 0; mt < 2; mt++)
#pragma unroll
        for (int nt = 0; nt < 8; nt++) {
            const int r = m0 + wm + mt * 16 + (lane >> 2);
            const int c = n0 + wn + nt * 8 + (lane & 3) * 2;
            *(float2*)&C[(size_t)r * PN2 + c] =
                make_float2(acc[mt][nt][0], acc[mt][nt][1]);
            *(float2*)&C[(size_t)(r + 8) * PN2 + c] =
                make_float2(acc[mt][nt][2], acc[mt][nt][3]);
        }
}

// tf32 split-K GEMM: h2 += [S | x_g2] @ [basis ; root] (B from g_Bt)
__global__ __launch_bounds__(256, 2) void gemm_acc_tf32(const float* __restrict__ xg2) {
    const int m0 = blockIdx.y * 128, n0 = blockIdx.x * 128;
    const int kt0 = blockIdx.z * KT_ACC;
    __shared__ float As[2 * 2560];
    __shared__ float Bs[2 * 2560];
    const int tid = threadIdx.x, lane = tid & 31, warp = tid >> 5;
    const int wm = (warp >> 1) * 32, wn = (warp & 1) * 64;
    const int mlo = tid >> 2, q4 = (tid & 3) * 4;
    const int s0 = (mlo * 20 + q4) * 4, s1 = ((mlo + 64) * 20 + q4) * 4;   // bytes
    const uint32_t AsU = smem_u32(As), BsU = smem_u32(Bs);
    const int base_a = ((wm + (lane & 15)) * 20 + (lane >> 4) * 4) * 4;
    const int base_b = ((wn + (lane & 7)) * 20 + (lane >> 3) * 4) * 4;

    auto issueStage = [&](int kt, int stg) {
        const uint32_t a_s = AsU + stg * 10240, b_s = BsU + stg * 10240;
        const float* Ab; int ko;
        if (kt < PNB * 64) { Ab = g_S + ((size_t)(kt >> 6) << 20); ko = (kt & 63) << 4; }
        else               { Ab = xg2; ko = (kt - PNB * 64) << 4; }
        const float* pa = Ab + (size_t)(m0 + mlo) * PN2 + ko + q4;
        cp16(a_s + s0, pa);
        cp16(a_s + s1, pa + (size_t)64 * PN2);
        const float* pb = g_Bt + ((size_t)(kt >> 6) << 20) +
                          (size_t)(n0 + mlo) * PN2 + ((kt & 63) << 4) + q4;
        cp16(b_s + s0, pb);
        cp16(b_s + s1, pb + (size_t)64 * PN2);
    };

    float acc[2][8][4];
#pragma unroll
    for (int i = 0; i < 2; i++)
#pragma unroll
        for (int j = 0; j < 8; j++)
#pragma unroll
            for (int k = 0; k < 4; k++) acc[i][j][k] = 0.0f;

    issueStage(kt0, 0);
    CP_COMMIT();

    for (int t = 0; t < KT_ACC; t++) {
        if (t + 1 < KT_ACC) {
            issueStage(kt0 + t + 1, (t + 1) & 1);
            CP_COMMIT();
            CP_WAIT1();
        } else {
            CP_WAIT0();
        }
        __syncthreads();
        const int cur = (t & 1) * 10240;
        gemm_compute_tile(AsU + cur, BsU + cur, base_a, base_b, acc);
        __syncthreads();
    }
#pragma unroll
    for (int mt = 0; mt < 2; mt++)
#pragma unroll
        for (int nt = 0; nt < 8; nt++) {
            const int r = m0 + wm + mt * 16 + (lane >> 2);
            const int c = n0 + wn + nt * 8 + (lane & 3) * 2;
            atomicAdd(&g_h2[(size_t)r * PN2 + c],           acc[mt][nt][0]);
            atomicAdd(&g_h2[(size_t)r * PN2 + c + 1],       acc[mt][nt][1]);
            atomicAdd(&g_h2[(size_t)(r + 8) * PN2 + c],     acc[mt][nt][2]);
            atomicAdd(&g_h2[(size_t)(r + 8) * PN2 + c + 1], acc[mt][nt][3]);
        }
}

// out2 = log_softmax(relu(h2 + bias)), one block per row
__global__ __launch_bounds__(256) void epilogue2_kernel(const float* __restrict__ bias,
                                                        float* __restrict__ out2) {
    const int row = blockIdx.x, tid = threadIdx.x;
    __shared__ float sred[8];
    __shared__ float sbcast;
    float4 v = *(const float4*)(g_h2 + (size_t)row * PN2 + tid * 4);
    float4 b = *(const float4*)(bias + tid * 4);
    v.x = fmaxf(v.x + b.x, 0.0f);
    v.y = fmaxf(v.y + b.y, 0.0f);
    v.z = fmaxf(v.z + b.z, 0.0f);
    v.w = fmaxf(v.w + b.w, 0.0f);
    float m = fmaxf(fmaxf(v.x, v.y), fmaxf(v.z, v.w));
#pragma unroll
    for (int o = 16; o; o >>= 1) m = fmaxf(m, __shfl_xor_sync(0xffffffffu, m, o));
    if ((tid & 31) == 0) sred[tid >> 5] = m;
    __syncthreads();
    if (tid == 0) {
        float t = sred[0];
#pragma unroll
        for (int i = 1; i < 8; i++) t = fmaxf(t, sred[i]);
        sbcast = t;
    }
    __syncthreads();
    m = sbcast;
    float s = __expf(v.x - m) + __expf(v.y - m) + __expf(v.z - m) + __expf(v.w - m);
#pragma unroll
    for (int o = 16; o; o >>= 1) s += __shfl_xor_sync(0xffffffffu, s, o);
    __syncthreads();
    if ((tid & 31) == 0) sred[tid >> 5] = s;
    __syncthreads();
    if (tid == 0) {
        float t = 0.0f;
#pragma unroll
        for (int i = 0; i < 8; i++) t += sred[i];
        sbcast = m + __logf(t);
    }
    __syncthreads();
    const float lse = sbcast;
    *(float4*)(out2 + (size_t)row * PN2 + tid * 4) =
        make_float4(v.x - lse, v.y - lse, v.z - lse, v.w - lse);
}

// =====================================================================
// launch — kernel launches ONLY
// =====================================================================
extern "C" void kernel_launch(void* const* d_in, const int* in_sizes, int n_in,
                              void* d_out, int out_size) {
    (void)in_sizes; (void)n_in; (void)out_size;
    const float* x_g1      = (const float*)d_in[0];
    const float* W_stc     = (const float*)d_in[1];
    const float* b_stc     = (const float*)d_in[2];
    const float* x_g2      = (const float*)d_in[3];
    const float* basis     = (const float*)d_in[4];
    const float* att       = (const float*)d_in[5];
    const float* root      = (const float*)d_in[6];
    const float* bias_rgcn = (const float*)d_in[7];
    const void*  ei1       = d_in[8];
    const void*  ei2       = d_in[9];
    const void*  et2       = d_in[10];
    float* out1 = (float*)d_out;
    float* out2 = out1 + (size_t)PN1 * PD;

    probe_kernel<<<1, 256>>>((const int*)ei1);
    zero_main_kernel<<<12500, 256>>>();
    zero_A_kernel<<<30720, 256>>>();

    // pre-transpose tf32 B operands
    {
        dim3 blk(32, 8);
        transpose_basis_kernel<<<dim3(32, 32, PNB), blk>>>(basis);
        transpose_root_kernel<<<dim3(32, 32), blk>>>(root);
        transpose_x_kernel<<<dim3(32, 32), blk>>>(x_g2);
    }

    // ---- Part 1 ----
    scatter1_kernel<<<PE1 / 8, 256>>>(x_g1, ei1);
    linear1_kernel<<<(PN1 + 63) / 64, 256>>>(W_stc, b_stc, out1);

    // ---- Part 2 ----
    deg2_kernel<<<(PE2 + 255) / 256, 256>>>(ei2);
    build_A_kernel<<<(PE2 + 255) / 256, 256>>>(ei2, et2, att);
    gemm1_tf32<<<dim3(8, 8, PNB), 256>>>();
    gemm_acc_tf32<<<dim3(8, 8, ZS_ACC), 256>>>(x_g2);
    epilogue2_kernel<<<PN2, 256>>>(bias_rgcn, out2);
}

// round 13
// speedup vs baseline: 3.4717x; 1.3077x over previous
#include <cuda_runtime.h>
#include <cuda_fp16.h>
#include <cstdint>

// ---------------- problem dimensions ----------------
#define PN1 100000
#define PE1 1600000
#define PD  128
#define PN2 1024
#define PE2 200000
#define PNB 30
#define ZS_ACC 8
#define KT_ACC 124            // (31744/32) / 8 K-tiles of 32 per split

// ---------------- device scratch ----------------
__device__ __align__(16) float  g_deg1[PN1];
__device__ __align__(16) float  g_agg1[(size_t)PN1 * PD];          // 51 MB
__device__ __align__(16) float  g_deg2[PN2];
__device__ __align__(16) float  g_A[(size_t)PNB * PN2 * PN2];      // 126 MB fp32 (atomic build)
__device__ __align__(16) __half g_Ah[(size_t)PNB * PN2 * PN2];     // 63 MB fp16 A
__device__ __align__(16) __half g_Sh[(size_t)PNB * PN2 * PN2];     // 63 MB fp16 S
__device__ __align__(16) __half g_Xth[(size_t)PN2 * PN2];          // x_g2^T fp16
__device__ __align__(16) __half g_Xh[(size_t)PN2 * PN2];           // x_g2 row-major fp16
__device__ __align__(16) __half g_Bth[(size_t)(PNB + 1) * PN2 * PN2]; // basis^T + root^T fp16
__device__ __align__(16) float  g_h2[(size_t)PN2 * PN2];
__device__ int g_is64;

// ---------------- helpers ----------------
__device__ __forceinline__ int load_idx(const void* p, size_t idx) {
    if (g_is64) return (int)((const long long*)p)[idx];
    return ((const int*)p)[idx];
}

__device__ __forceinline__ uint32_t smem_u32(const void* p) {
    uint32_t r;
    asm("{ .reg .u64 t; cvta.to.shared.u64 t, %1; cvt.u32.u64 %0, t; }"
        : "=r"(r) : "l"(p));
    return r;
}

__device__ __forceinline__ void ldsm4(uint32_t& r0, uint32_t& r1, uint32_t& r2,
                                      uint32_t& r3, uint32_t addr) {
    asm volatile("ldmatrix.sync.aligned.m8n8.x4.shared.b16 {%0,%1,%2,%3}, [%4];"
                 : "=r"(r0), "=r"(r1), "=r"(r2), "=r"(r3) : "r"(addr));
}

__device__ __forceinline__ void mma_f16(float* c, uint32_t a0, uint32_t a1,
                                        uint32_t a2, uint32_t a3,
                                        uint32_t b0, uint32_t b1) {
    asm volatile(
        "mma.sync.aligned.m16n8k16.row.col.f32.f16.f16.f32 "
        "{%0,%1,%2,%3},{%4,%5,%6,%7},{%8,%9},{%0,%1,%2,%3};"
        : "+f"(c[0]), "+f"(c[1]), "+f"(c[2]), "+f"(c[3])
        : "r"(a0), "r"(a1), "r"(a2), "r"(a3), "r"(b0), "r"(b1));
}

__device__ __forceinline__ void cp16(uint32_t s, const void* g) {
    asm volatile("cp.async.cg.shared.global [%0], [%1], 16;" :: "r"(s), "l"(g));
}
#define CP_COMMIT() asm volatile("cp.async.commit_group;")
#define CP_WAIT1()  asm volatile("cp.async.wait_group 1;")
#define CP_WAIT0()  asm volatile("cp.async.wait_group 0;")

// fp16 compute core: 128x128 CTA tile, 8 warps (4m x 2n), warp tile 32x64,
// K-tile 32 (two k16 steps). Smem rows: 32 halves payload, stride 80 B
// (bank quads 20r mod 32 all distinct -> conflict-free ldmatrix).
__device__ __forceinline__ void compute_k32(uint32_t AsU, uint32_t BsU,
                                            int base_a, int base_b,
                                            float (&acc)[2][8][4]) {
#pragma unroll
    for (int ks = 0; ks < 2; ks++) {
        uint32_t a[2][4];
        ldsm4(a[0][0], a[0][1], a[0][2], a[0][3], AsU + base_a + ks * 32);
        ldsm4(a[1][0], a[1][1], a[1][2], a[1][3], AsU + base_a + 16 * 80 + ks * 32);
#pragma unroll
        for (int j = 0; j < 4; j++) {
            uint32_t b0, b1, b2, b3;
            ldsm4(b0, b1, b2, b3, BsU + base_b + j * (16 * 80) + ks * 32);
            mma_f16(acc[0][2 * j],     a[0][0], a[0][1], a[0][2], a[0][3], b0, b2);
            mma_f16(acc[0][2 * j + 1], a[0][0], a[0][1], a[0][2], a[0][3], b1, b3);
            mma_f16(acc[1][2 * j],     a[1][0], a[1][1], a[1][2], a[1][3], b0, b2);
            mma_f16(acc[1][2 * j + 1], a[1][0], a[1][1], a[1][2], a[1][3], b1, b3);
        }
    }
}

// =====================================================================
// probe / zero / transposes / converts
// =====================================================================
__global__ void probe_kernel(const int* __restrict__ ei_words) {
    __shared__ int found;
    if (threadIdx.x == 0) found = 0;
    __syncthreads();
    for (int i = threadIdx.x; i < 4096; i += 256)
        if (ei_words[2 * i + 1] != 0) found = 1;
    __syncthreads();
    if (threadIdx.x == 0) g_is64 = found ? 0 : 1;
}

__global__ void zero_main_kernel() {
    const size_t i = (size_t)blockIdx.x * blockDim.x + threadIdx.x;
    const float4 z = make_float4(0.f, 0.f, 0.f, 0.f);
    if (i < (size_t)PN1 * PD / 4)  ((float4*)g_agg1)[i] = z;
    if (i < PN1 / 4)               ((float4*)g_deg1)[i] = z;
    if (i < (size_t)PN2 * PN2 / 4) ((float4*)g_h2)[i] = z;
    if (i < PN2 / 4)               ((float4*)g_deg2)[i] = z;
}

__global__ void zero_A_kernel() {
    const size_t i = (size_t)blockIdx.x * blockDim.x + threadIdx.x;
    if (i < (size_t)PNB * PN2 * PN2 / 4)
        ((float4*)g_A)[i] = make_float4(0.f, 0.f, 0.f, 0.f);
}

__device__ __forceinline__ void transpose_core_h(__half* dst,
                                                 const float* __restrict__ src) {
    __shared__ float tile[32][33];
    int c = blockIdx.x * 32 + threadIdx.x;
    int r = blockIdx.y * 32 + threadIdx.y;
#pragma unroll
    for (int i = 0; i < 32; i += 8)
        tile[threadIdx.y + i][threadIdx.x] = src[(size_t)(r + i) * PN2 + c];
    __syncthreads();
    c = blockIdx.y * 32 + threadIdx.x;
    r = blockIdx.x * 32 + threadIdx.y;
#pragma unroll
    for (int i = 0; i < 32; i += 8)
        dst[(size_t)(r + i) * PN2 + c] = __float2half_rn(tile[threadIdx.x][threadIdx.y + i]);
}

__global__ void transpose_basis_kernel(const float* __restrict__ src) {
    const size_t zoff = (size_t)blockIdx.z << 20;
    transpose_core_h(g_Bth + zoff, src + zoff);
}
__global__ void transpose_root_kernel(const float* __restrict__ src) {
    transpose_core_h(g_Bth + ((size_t)PNB << 20), src);
}
__global__ void transpose_x_kernel(const float* __restrict__ src) {
    transpose_core_h(g_Xth, src);
}

// fp32 -> fp16, 8 elements (16B out) per thread
__global__ void convert_A_kernel() {
    const size_t i = (size_t)blockIdx.x * blockDim.x + threadIdx.x;
    if (i >= ((size_t)PNB << 20) / 8) return;
    float4 f0 = ((const float4*)g_A)[2 * i];
    float4 f1 = ((const float4*)g_A)[2 * i + 1];
    __half2 h[4];
    h[0] = __floats2half2_rn(f0.x, f0.y);
    h[1] = __floats2half2_rn(f0.z, f0.w);
    h[2] = __floats2half2_rn(f1.x, f1.y);
    h[3] = __floats2half2_rn(f1.z, f1.w);
    ((float4*)g_Ah)[i] = *(float4*)h;
}

__global__ void convert_X_kernel(const float* __restrict__ x) {
    const size_t i = (size_t)blockIdx.x * blockDim.x + threadIdx.x;
    if (i >= ((size_t)PN2 * PN2) / 8) return;
    float4 f0 = ((const float4*)x)[2 * i];
    float4 f1 = ((const float4*)x)[2 * i + 1];
    __half2 h[4];
    h[0] = __floats2half2_rn(f0.x, f0.y);
    h[1] = __floats2half2_rn(f0.z, f0.w);
    h[2] = __floats2half2_rn(f1.x, f1.y);
    h[3] = __floats2half2_rn(f1.z, f1.w);
    ((float4*)g_Xh)[i] = *(float4*)h;
}

// =====================================================================
// Part 1: STCConv
// =====================================================================
__global__ void scatter1_kernel(const float* __restrict__ x,
                                const void* __restrict__ ei) {
    const unsigned gw = (blockIdx.x * blockDim.x + threadIdx.x) >> 5;
    const int lane = threadIdx.x & 31;
    if (gw >= PE1) return;
    const int s = load_idx(ei, gw);
    const int d = load_idx(ei, (size_t)PE1 + gw);
    float4 v = *(const float4*)(x + (size_t)s * PD + lane * 4);
    float* a = g_agg1 + (size_t)d * PD + lane * 4;
    asm volatile("red.global.add.v4.f32 [%0], {%1,%2,%3,%4};"
                 :: "l"(a), "f"(v.x), "f"(v.y), "f"(v.z), "f"(v.w) : "memory");
    if (lane == 0) atomicAdd(&g_deg1[d], 1.0f);
}

__global__ __launch_bounds__(256) void linear1_kernel(const float* __restrict__ W,
                                                      const float* __restrict__ bias,
                                                      float* __restrict__ out1) {
    __shared__ float Ws[64 * 128];
    const int tid = threadIdx.x;
    const int lane = tid & 31;
    const int warp = tid >> 5;
    const int row0 = blockIdx.x * 64 + warp * 8;
    const int nrow = max(0, min(8, PN1 - row0));
    const float4 bv = *(const float4*)(bias + lane * 4);

    float acc[8][4];
#pragma unroll
    for (int r = 0; r < 8; r++) {
        acc[r][0] = bv.x; acc[r][1] = bv.y; acc[r][2] = bv.z; acc[r][3] = bv.w;
    }

#pragma unroll 1
    for (int half = 0; half < 2; half++) {
        __syncthreads();
        for (int i = tid; i < 2048; i += 256)
            ((float4*)Ws)[i] = ((const float4*)W)[half * 2048 + i];
        __syncthreads();

        float4 vr[8];
#pragma unroll
        for (int r = 0; r < 8; r++) {
            const int row = row0 + r;
            if (row < PN1) {
                const float invd = 1.0f / fmaxf(g_deg1[row], 1.0f);
                float4 v = *(const float4*)(g_agg1 + (size_t)row * PD +
                                            half * 64 + (lane & 15) * 4);
                vr[r] = make_float4(v.x * invd, v.y * invd, v.z * invd, v.w * invd);
            } else {
                vr[r] = make_float4(0.f, 0.f, 0.f, 0.f);
            }
        }
#pragma unroll
        for (int k4 = 0; k4 < 16; k4++) {
            const float* wp = Ws + (k4 * 4) * PD + lane * 4;
            float4 w0 = *(const float4*)(wp);
            float4 w1 = *(const float4*)(wp + PD);
            float4 w2 = *(const float4*)(wp + 2 * PD);
            float4 w3 = *(const float4*)(wp + 3 * PD);
#pragma unroll
            for (int r = 0; r < 8; r++) {
                float r0 = __shfl_sync(0xffffffffu, vr[r].x, k4);
                float r1 = __shfl_sync(0xffffffffu, vr[r].y, k4);
                float r2 = __shfl_sync(0xffffffffu, vr[r].z, k4);
                float r3 = __shfl_sync(0xffffffffu, vr[r].w, k4);
                acc[r][0] += r0 * w0.x + r1 * w1.x + r2 * w2.x + r3 * w3.x;
                acc[r][1] += r0 * w0.y + r1 * w1.y + r2 * w2.y + r3 * w3.y;
                acc[r][2] += r0 * w0.z + r1 * w1.z + r2 * w2.z + r3 * w3.z;
                acc[r][3] += r0 * w0.w + r1 * w1.w + r2 * w2.w + r3 * w3.w;
            }
        }
    }

    for (int r = 0; r < nrow; r++) {
        float a0 = fmaxf(acc[r][0], 0.0f), a1 = fmaxf(acc[r][1], 0.0f);
        float a2 = fmaxf(acc[r][2], 0.0f), a3 = fmaxf(acc[r][3], 0.0f);
        float m = fmaxf(fmaxf(a0, a1), fmaxf(a2, a3));
#pragma unroll
        for (int o = 16; o; o >>= 1) m = fmaxf(m, __shfl_xor_sync(0xffffffffu, m, o));
        float s = __expf(a0 - m) + __expf(a1 - m) + __expf(a2 - m) + __expf(a3 - m);
#pragma unroll
        for (int o = 16; o; o >>= 1) s += __shfl_xor_sync(0xffffffffu, s, o);
        float lse = m + __logf(s);
        *(float4*)(out1 + (size_t)(row0 + r) * PD + lane * 4) =
            make_float4(a0 - lse, a1 - lse, a2 - lse, a3 - lse);
    }
}

// =====================================================================
// Part 2: densified RGCN (fp16 tensor cores)
// =====================================================================
__global__ void deg2_kernel(const void* __restrict__ ei) {
    int e = blockIdx.x * blockDim.x + threadIdx.x;
    if (e < PE2) atomicAdd(&g_deg2[load_idx(ei, (size_t)PE2 + e)], 1.0f);
}

__global__ void build_A_kernel(const void* __restrict__ ei,
                               const void* __restrict__ et,
                               const float* __restrict__ att) {
    int e = blockIdx.x * blockDim.x + threadIdx.x;
    if (e >= PE2) return;
    const int s = load_idx(ei, e);
    const int d = load_idx(ei, (size_t)PE2 + e);
    const int t = load_idx(et, e);
    const float w = 1.0f / fmaxf(g_deg2[d], 1.0f);
    const float* ar = att + (size_t)t * PNB;
    float* base = g_A + (size_t)d * PN2 + s;
#pragma unroll
    for (int b = 0; b < PNB; b++)
        atomicAdd(base + ((size_t)b << 20), ar[b] * w);
}

// fp16 batched GEMM: S[z] = A[z] @ X   (A from g_Ah, B from g_Xth)
__global__ __launch_bounds__(256, 2) void gemm1_f16() {
    const int z = blockIdx.z;
    const __half* A = g_Ah + ((size_t)z << 20);
    __half* C = g_Sh + ((size_t)z << 20);
    const int m0 = blockIdx.y * 128, n0 = blockIdx.x * 128;
    __shared__ __half As[2 * 5120];    // 2 stages x 128 rows x 40-half stride
    __shared__ __half Bs[2 * 5120];
    const int tid = threadIdx.x, lane = tid & 31, warp = tid >> 5;
    const int wm = (warp >> 1) * 32, wn = (warp & 1) * 64;
    const int r = tid >> 1, co = (tid & 1) * 16;      // halves within 32-K tile
    const uint32_t sdst = r * 80 + (tid & 1) * 32;    // bytes
    const uint32_t AsU = smem_u32(As), BsU = smem_u32(Bs);
    const __half* ap = A + (size_t)(m0 + r) * PN2 + co;
    const __half* bp = g_Xth + (size_t)(n0 + r) * PN2 + co;
    const int base_a = (wm + (lane & 15)) * 80 + (lane >> 4) * 16;
    const int base_b = (wn + (lane & 15)) * 80 + (lane >> 4) * 16;

    float acc[2][8][4];
#pragma unroll
    for (int i = 0; i < 2; i++)
#pragma unroll
        for (int j = 0; j < 8; j++)
#pragma unroll
            for (int k = 0; k < 4; k++) acc[i][j][k] = 0.0f;

    cp16(AsU + sdst, ap); cp16(AsU + sdst + 16, ap + 8);
    cp16(BsU + sdst, bp); cp16(BsU + sdst + 16, bp + 8);
    CP_COMMIT();

    const int NT = 32;   // 1024 / 32
    for (int t = 0; t < NT; t++) {
        if (t + 1 < NT) {
            const uint32_t nx = ((t + 1) & 1) * 10240;
            const int ko = (t + 1) * 32;
            cp16(AsU + nx + sdst, ap + ko); cp16(AsU + nx + sdst + 16, ap + ko + 8);
            cp16(BsU + nx + sdst, bp + ko); cp16(BsU + nx + sdst + 16, bp + ko + 8);
            CP_COMMIT(); CP_WAIT1();
        } else {
            CP_WAIT0();
        }
        __syncthreads();
        const uint32_t cur = (t & 1) * 10240;
        compute_k32(AsU + cur, BsU + cur, base_a, base_b, acc);
        __syncthreads();
    }
#pragma unroll
    for (int mt = 0; mt < 2; mt++)
#pragma unroll
        for (int nt = 0; nt < 8; nt++) {
            const int rr = m0 + wm + mt * 16 + (lane >> 2);
            const int cc = n0 + wn + nt * 8 + (lane & 3) * 2;
            *(__half2*)&C[(size_t)rr * PN2 + cc] =
                __floats2half2_rn(acc[mt][nt][0], acc[mt][nt][1]);
            *(__half2*)&C[(size_t)(rr + 8) * PN2 + cc] =
                __floats2half2_rn(acc[mt][nt][2], acc[mt][nt][3]);
        }
}

// fp16 split-K GEMM: h2 += [S | x_g2] @ [basis ; root]
__global__ __launch_bounds__(256, 2) void gemm_acc_f16() {
    const int m0 = blockIdx.y * 128, n0 = blockIdx.x * 128;
    const int kt0 = blockIdx.z * KT_ACC;
    __shared__ __half As[2 * 5120];
    __shared__ __half Bs[2 * 5120];
    const int tid = threadIdx.x, lane = tid & 31, warp = tid >> 5;
    const int wm = (warp >> 1) * 32, wn = (warp & 1) * 64;
    const int r = tid >> 1, co = (tid & 1) * 16;
    const uint32_t sdst = r * 80 + (tid & 1) * 32;
    const uint32_t AsU = smem_u32(As), BsU = smem_u32(Bs);
    const int base_a = (wm + (lane & 15)) * 80 + (lane >> 4) * 16;
    const int base_b = (wn + (lane & 15)) * 80 + (lane >> 4) * 16;

    auto srcA = [&](int kt) -> const __half* {
        if (kt < PNB * 32)
            return g_Sh + ((size_t)(kt >> 5) << 20) + (size_t)(m0 + r) * PN2 +
                   ((kt & 31) << 5) + co;
        return g_Xh + (size_t)(m0 + r) * PN2 + ((kt - PNB * 32) << 5) + co;
    };
    auto srcB = [&](int kt) -> const __half* {
        return g_Bth + ((size_t)(kt >> 5) << 20) + (size_t)(n0 + r) * PN2 +
               ((kt & 31) << 5) + co;
    };

    float acc[2][8][4];
#pragma unroll
    for (int i = 0; i < 2; i++)
#pragma unroll
        for (int j = 0; j < 8; j++)
#pragma unroll
            for (int k = 0; k < 4; k++) acc[i][j][k] = 0.0f;

    {
        const __half* pa = srcA(kt0);
        const __half* pb = srcB(kt0);
        cp16(AsU + sdst, pa); cp16(AsU + sdst + 16, pa + 8);
        cp16(BsU + sdst, pb); cp16(BsU + sdst + 16, pb + 8);
        CP_COMMIT();
    }

    for (int t = 0; t < KT_ACC; t++) {
        if (t + 1 < KT_ACC) {
            const uint32_t nx = ((t + 1) & 1) * 10240;
            const __half* pa = srcA(kt0 + t + 1);
            const __half* pb = srcB(kt0 + t + 1);
            cp16(AsU + nx + sdst, pa); cp16(AsU + nx + sdst + 16, pa + 8);
            cp16(BsU + nx + sdst, pb); cp16(BsU + nx + sdst + 16, pb + 8);
            CP_COMMIT(); CP_WAIT1();
        } else {
            CP_WAIT0();
        }
        __syncthreads();
        const uint32_t cur = (t & 1) * 10240;
        compute_k32(AsU + cur, BsU + cur, base_a, base_b, acc);
        __syncthreads();
    }
#pragma unroll
    for (int mt = 0; mt < 2; mt++)
#pragma unroll
        for (int nt = 0; nt < 8; nt++) {
            const int rr = m0 + wm + mt * 16 + (lane >> 2);
            const int cc = n0 + wn + nt * 8 + (lane & 3) * 2;
            atomicAdd(&g_h2[(size_t)rr * PN2 + cc],           acc[mt][nt][0]);
            atomicAdd(&g_h2[(size_t)rr * PN2 + cc + 1],       acc[mt][nt][1]);
            atomicAdd(&g_h2[(size_t)(rr + 8) * PN2 + cc],     acc[mt][nt][2]);
            atomicAdd(&g_h2[(size_t)(rr + 8) * PN2 + cc + 1], acc[mt][nt][3]);
        }
}

// out2 = log_softmax(relu(h2 + bias)), one block per row
__global__ __launch_bounds__(256) void epilogue2_kernel(const float* __restrict__ bias,
                                                        float* __restrict__ out2) {
    const int row = blockIdx.x, tid = threadIdx.x;
    __shared__ float sred[8];
    __shared__ float sbcast;
    float4 v = *(const float4*)(g_h2 + (size_t)row * PN2 + tid * 4);
    float4 b = *(const float4*)(bias + tid * 4);
    v.x = fmaxf(v.x + b.x, 0.0f);
    v.y = fmaxf(v.y + b.y, 0.0f);
    v.z = fmaxf(v.z + b.z, 0.0f);
    v.w = fmaxf(v.w + b.w, 0.0f);
    float m = fmaxf(fmaxf(v.x, v.y), fmaxf(v.z, v.w));
#pragma unroll
    for (int o = 16; o; o >>= 1) m = fmaxf(m, __shfl_xor_sync(0xffffffffu, m, o));
    if ((tid & 31) == 0) sred[tid >> 5] = m;
    __syncthreads();
    if (tid == 0) {
        float t = sred[0];
#pragma unroll
        for (int i = 1; i < 8; i++) t = fmaxf(t, sred[i]);
        sbcast = t;
    }
    __syncthreads();
    m = sbcast;
    float s = __expf(v.x - m) + __expf(v.y - m) + __expf(v.z - m) + __expf(v.w - m);
#pragma unroll
    for (int o = 16; o; o >>= 1) s += __shfl_xor_sync(0xffffffffu, s, o);
    __syncthreads();
    if ((tid & 31) == 0) sred[tid >> 5] = s;
    __syncthreads();
    if (tid == 0) {
        float t = 0.0f;
#pragma unroll
        for (int i = 0; i < 8; i++) t += sred[i];
        sbcast = m + __logf(t);
    }
    __syncthreads();
    const float lse = sbcast;
    *(float4*)(out2 + (size_t)row * PN2 + tid * 4) =
        make_float4(v.x - lse, v.y - lse, v.z - lse, v.w - lse);
}

// =====================================================================
// launch — kernel launches ONLY
// =====================================================================
extern "C" void kernel_launch(void* const* d_in, const int* in_sizes, int n_in,
                              void* d_out, int out_size) {
    (void)in_sizes; (void)n_in; (void)out_size;
    const float* x_g1      = (const float*)d_in[0];
    const float* W_stc     = (const float*)d_in[1];
    const float* b_stc     = (const float*)d_in[2];
    const float* x_g2      = (const float*)d_in[3];
    const float* basis     = (const float*)d_in[4];
    const float* att       = (const float*)d_in[5];
    const float* root      = (const float*)d_in[6];
    const float* bias_rgcn = (const float*)d_in[7];
    const void*  ei1       = d_in[8];
    const void*  ei2       = d_in[9];
    const void*  et2       = d_in[10];
    float* out1 = (float*)d_out;
    float* out2 = out1 + (size_t)PN1 * PD;

    probe_kernel<<<1, 256>>>((const int*)ei1);
    zero_main_kernel<<<12500, 256>>>();
    zero_A_kernel<<<30720, 256>>>();

    // fp16 operand preparation
    {
        dim3 blk(32, 8);
        transpose_basis_kernel<<<dim3(32, 32, PNB), blk>>>(basis);
        transpose_root_kernel<<<dim3(32, 32), blk>>>(root);
        transpose_x_kernel<<<dim3(32, 32), blk>>>(x_g2);
    }
    convert_X_kernel<<<512, 256>>>(x_g2);

    // ---- Part 1 ----
    scatter1_kernel<<<PE1 / 8, 256>>>(x_g1, ei1);
    linear1_kernel<<<(PN1 + 63) / 64, 256>>>(W_stc, b_stc, out1);

    // ---- Part 2 ----
    deg2_kernel<<<(PE2 + 255) / 256, 256>>>(ei2);
    build_A_kernel<<<(PE2 + 255) / 256, 256>>>(ei2, et2, att);
    convert_A_kernel<<<15360, 256>>>();
    gemm1_f16<<<dim3(8, 8, PNB), 256>>>();
    gemm_acc_f16<<<dim3(8, 8, ZS_ACC), 256>>>();
    epilogue2_kernel<<<PN2, 256>>>(bias_rgcn, out2);
}

// round 15
// speedup vs baseline: 3.6604x; 1.0543x over previous
#include <cuda_runtime.h>
#include <cuda_fp16.h>
#include <cstdint>

// ---------------- problem dimensions ----------------
#define PN1 100000
#define PE1 1600000
#define PD  128
#define PN2 1024
#define PE2 200000
#define PNB 30
#define ZS_ACC 8
#define KT_ACC 248            // (31744/16) / 8 K-tiles of 16 per split

// smem geometry: rows of 16 halves padded to 48 B (16B-aligned for cp.async,
// bank-quads 12r mod 32 all distinct -> conflict-free ldmatrix)
#define ROW_B 48
#define STAGE_B (128 * ROW_B)   // 6144 bytes per matrix per stage

// ---------------- device scratch ----------------
__device__ __align__(16) float  g_deg1[PN1];
__device__ __align__(16) float  g_agg1[(size_t)PN1 * PD];          // 51 MB
__device__ __align__(16) float  g_deg2[PN2];
__device__ __align__(16) __half g_Ah[(size_t)PNB * PN2 * PN2];     // 63 MB fp16 A (atomic build)
__device__ __align__(16) __half g_Sh[(size_t)PNB * PN2 * PN2];     // 63 MB fp16 S
__device__ __align__(16) __half g_Xth[(size_t)PN2 * PN2];          // x_g2^T fp16
__device__ __align__(16) __half g_Xh[(size_t)PN2 * PN2];           // x_g2 row-major fp16
__device__ __align__(16) __half g_Bth[(size_t)(PNB + 1) * PN2 * PN2]; // basis^T + root^T fp16
__device__ __align__(16) float  g_h2[(size_t)PN2 * PN2];
__device__ int g_is64;

// ---------------- helpers ----------------
__device__ __forceinline__ int load_idx(const void* p, size_t idx) {
    if (g_is64) return (int)((const long long*)p)[idx];
    return ((const int*)p)[idx];
}

__device__ __forceinline__ uint32_t smem_u32(const void* p) {
    uint32_t r;
    asm("{ .reg .u64 t; cvta.to.shared.u64 t, %1; cvt.u32.u64 %0, t; }"
        : "=r"(r) : "l"(p));
    return r;
}

__device__ __forceinline__ void ldsm4(uint32_t& r0, uint32_t& r1, uint32_t& r2,
                                      uint32_t& r3, uint32_t addr) {
    asm volatile("ldmatrix.sync.aligned.m8n8.x4.shared.b16 {%0,%1,%2,%3}, [%4];"
                 : "=r"(r0), "=r"(r1), "=r"(r2), "=r"(r3) : "r"(addr));
}

__device__ __forceinline__ void mma_f16(float* c, uint32_t a0, uint32_t a1,
                                        uint32_t a2, uint32_t a3,
                                        uint32_t b0, uint32_t b1) {
    asm volatile(
        "mma.sync.aligned.m16n8k16.row.col.f32.f16.f16.f32 "
        "{%0,%1,%2,%3},{%4,%5,%6,%7},{%8,%9},{%0,%1,%2,%3};"
        : "+f"(c[0]), "+f"(c[1]), "+f"(c[2]), "+f"(c[3])
        : "r"(a0), "r"(a1), "r"(a2), "r"(a3), "r"(b0), "r"(b1));
}

__device__ __forceinline__ void cp16(uint32_t s, const void* g) {
    asm volatile("cp.async.cg.shared.global [%0], [%1], 16;" :: "r"(s), "l"(g));
}
#define CP_COMMIT() asm volatile("cp.async.commit_group;")
#define CP_WAIT2()  asm volatile("cp.async.wait_group 2;")

// fp16 compute core: 128x128 CTA tile, 8 warps (4m x 2n), warp tile 32x64,
// K-tile 16.
__device__ __forceinline__ void compute_k16(uint32_t AsU, uint32_t BsU,
                                            int base_a, int base_b,
                                            float (&acc)[2][8][4]) {
    uint32_t a[2][4];
    ldsm4(a[0][0], a[0][1], a[0][2], a[0][3], AsU + base_a);
    ldsm4(a[1][0], a[1][1], a[1][2], a[1][3], AsU + base_a + 16 * ROW_B);
#pragma unroll
    for (int j = 0; j < 4; j++) {
        uint32_t b0, b1, b2, b3;
        ldsm4(b0, b1, b2, b3, BsU + base_b + j * (16 * ROW_B));
        mma_f16(acc[0][2 * j],     a[0][0], a[0][1], a[0][2], a[0][3], b0, b2);
        mma_f16(acc[0][2 * j + 1], a[0][0], a[0][1], a[0][2], a[0][3], b1, b3);
        mma_f16(acc[1][2 * j],     a[1][0], a[1][1], a[1][2], a[1][3], b0, b2);
        mma_f16(acc[1][2 * j + 1], a[1][0], a[1][1], a[1][2], a[1][3], b1, b3);
    }
}

// =====================================================================
// probe / zero / transposes / converts
// =====================================================================
__global__ void probe_kernel(const int* __restrict__ ei_words) {
    __shared__ int found;
    if (threadIdx.x == 0) found = 0;
    __syncthreads();
    for (int i = threadIdx.x; i < 4096; i += 256)
        if (ei_words[2 * i + 1] != 0) found = 1;
    __syncthreads();
    if (threadIdx.x == 0) g_is64 = found ? 0 : 1;
}

__global__ void zero_main_kernel() {
    const size_t i = (size_t)blockIdx.x * blockDim.x + threadIdx.x;
    const float4 z = make_float4(0.f, 0.f, 0.f, 0.f);
    if (i < (size_t)PN1 * PD / 4)  ((float4*)g_agg1)[i] = z;
    if (i < PN1 / 4)               ((float4*)g_deg1)[i] = z;
    if (i < (size_t)PN2 * PN2 / 4) ((float4*)g_h2)[i] = z;
    if (i < PN2 / 4)               ((float4*)g_deg2)[i] = z;
}

__global__ void zero_Ah_kernel() {
    const size_t i = (size_t)blockIdx.x * blockDim.x + threadIdx.x;
    if (i < ((size_t)PNB << 20) / 8)
        ((float4*)g_Ah)[i] = make_float4(0.f, 0.f, 0.f, 0.f);
}

__device__ __forceinline__ void transpose_core_h(__half* dst,
                                                 const float* __restrict__ src) {
    __shared__ float tile[32][33];
    int c = blockIdx.x * 32 + threadIdx.x;
    int r = blockIdx.y * 32 + threadIdx.y;
#pragma unroll
    for (int i = 0; i < 32; i += 8)
        tile[threadIdx.y + i][threadIdx.x] = src[(size_t)(r + i) * PN2 + c];
    __syncthreads();
    c = blockIdx.y * 32 + threadIdx.x;
    r = blockIdx.x * 32 + threadIdx.y;
#pragma unroll
    for (int i = 0; i < 32; i += 8)
        dst[(size_t)(r + i) * PN2 + c] = __float2half_rn(tile[threadIdx.x][threadIdx.y + i]);
}

__global__ void transpose_basis_kernel(const float* __restrict__ src) {
    const size_t zoff = (size_t)blockIdx.z << 20;
    transpose_core_h(g_Bth + zoff, src + zoff);
}
__global__ void transpose_root_kernel(const float* __restrict__ src) {
    transpose_core_h(g_Bth + ((size_t)PNB << 20), src);
}
__global__ void transpose_x_kernel(const float* __restrict__ src) {
    transpose_core_h(g_Xth, src);
}

__global__ void convert_X_kernel(const float* __restrict__ x) {
    const size_t i = (size_t)blockIdx.x * blockDim.x + threadIdx.x;
    if (i >= ((size_t)PN2 * PN2) / 8) return;
    float4 f0 = ((const float4*)x)[2 * i];
    float4 f1 = ((const float4*)x)[2 * i + 1];
    __half2 h[4];
    h[0] = __floats2half2_rn(f0.x, f0.y);
    h[1] = __floats2half2_rn(f0.z, f0.w);
    h[2] = __floats2half2_rn(f1.x, f1.y);
    h[3] = __floats2half2_rn(f1.z, f1.w);
    ((float4*)g_Xh)[i] = *(float4*)h;
}

// =====================================================================
// Part 1: STCConv
// =====================================================================
__global__ void scatter1_kernel(const float* __restrict__ x,
                                const void* __restrict__ ei) {
    const unsigned gw = (blockIdx.x * blockDim.x + threadIdx.x) >> 5;
    const int lane = threadIdx.x & 31;
    if (gw >= PE1) return;
    const int s = load_idx(ei, gw);
    const int d = load_idx(ei, (size_t)PE1 + gw);
    float4 v = *(const float4*)(x + (size_t)s * PD + lane * 4);
    float* a = g_agg1 + (size_t)d * PD + lane * 4;
    asm volatile("red.global.add.v4.f32 [%0], {%1,%2,%3,%4};"
                 :: "l"(a), "f"(v.x), "f"(v.y), "f"(v.z), "f"(v.w) : "memory");
    if (lane == 0) atomicAdd(&g_deg1[d], 1.0f);
}

__global__ __launch_bounds__(256) void linear1_kernel(const float* __restrict__ W,
                                                      const float* __restrict__ bias,
                                                      float* __restrict__ out1) {
    __shared__ float Ws[64 * 128];
    const int tid = threadIdx.x;
    const int lane = tid & 31;
    const int warp = tid >> 5;
    const int row0 = blockIdx.x * 64 + warp * 8;
    const int nrow = max(0, min(8, PN1 - row0));
    const float4 bv = *(const float4*)(bias + lane * 4);

    float acc[8][4];
#pragma unroll
    for (int r = 0; r < 8; r++) {
        acc[r][0] = bv.x; acc[r][1] = bv.y; acc[r][2] = bv.z; acc[r][3] = bv.w;
    }

#pragma unroll 1
    for (int half = 0; half < 2; half++) {
        __syncthreads();
        for (int i = tid; i < 2048; i += 256)
            ((float4*)Ws)[i] = ((const float4*)W)[half * 2048 + i];
        __syncthreads();

        float4 vr[8];
#pragma unroll
        for (int r = 0; r < 8; r++) {
            const int row = row0 + r;
            if (row < PN1) {
                const float invd = 1.0f / fmaxf(g_deg1[row], 1.0f);
                float4 v = *(const float4*)(g_agg1 + (size_t)row * PD +
                                            half * 64 + (lane & 15) * 4);
                vr[r] = make_float4(v.x * invd, v.y * invd, v.z * invd, v.w * invd);
            } else {
                vr[r] = make_float4(0.f, 0.f, 0.f, 0.f);
            }
        }
#pragma unroll
        for (int k4 = 0; k4 < 16; k4++) {
            const float* wp = Ws + (k4 * 4) * PD + lane * 4;
            float4 w0 = *(const float4*)(wp);
            float4 w1 = *(const float4*)(wp + PD);
            float4 w2 = *(const float4*)(wp + 2 * PD);
            float4 w3 = *(const float4*)(wp + 3 * PD);
#pragma unroll
            for (int r = 0; r < 8; r++) {
                float r0 = __shfl_sync(0xffffffffu, vr[r].x, k4);
                float r1 = __shfl_sync(0xffffffffu, vr[r].y, k4);
                float r2 = __shfl_sync(0xffffffffu, vr[r].z, k4);
                float r3 = __shfl_sync(0xffffffffu, vr[r].w, k4);
                acc[r][0] += r0 * w0.x + r1 * w1.x + r2 * w2.x + r3 * w3.x;
                acc[r][1] += r0 * w0.y + r1 * w1.y + r2 * w2.y + r3 * w3.y;
                acc[r][2] += r0 * w0.z + r1 * w1.z + r2 * w2.z + r3 * w3.z;
                acc[r][3] += r0 * w0.w + r1 * w1.w + r2 * w2.w + r3 * w3.w;
            }
        }
    }

    for (int r = 0; r < nrow; r++) {
        float a0 = fmaxf(acc[r][0], 0.0f), a1 = fmaxf(acc[r][1], 0.0f);
        float a2 = fmaxf(acc[r][2], 0.0f), a3 = fmaxf(acc[r][3], 0.0f);
        float m = fmaxf(fmaxf(a0, a1), fmaxf(a2, a3));
#pragma unroll
        for (int o = 16; o; o >>= 1) m = fmaxf(m, __shfl_xor_sync(0xffffffffu, m, o));
        float s = __expf(a0 - m) + __expf(a1 - m) + __expf(a2 - m) + __expf(a3 - m);
#pragma unroll
        for (int o = 16; o; o >>= 1) s += __shfl_xor_sync(0xffffffffu, s, o);
        float lse = m + __logf(s);
        *(float4*)(out1 + (size_t)(row0 + r) * PD + lane * 4) =
            make_float4(a0 - lse, a1 - lse, a2 - lse, a3 - lse);
    }
}

// =====================================================================
// Part 2: densified RGCN (fp16 tensor cores)
// =====================================================================
__global__ void deg2_kernel(const void* __restrict__ ei) {
    int e = blockIdx.x * blockDim.x + threadIdx.x;
    if (e < PE2) atomicAdd(&g_deg2[load_idx(ei, (size_t)PE2 + e)], 1.0f);
}

// A built directly in fp16 (values ~5e-3, few collisions -> fp16-safe)
__global__ void build_A_f16_kernel(const void* __restrict__ ei,
                                   const void* __restrict__ et,
                                   const float* __restrict__ att) {
    int e = blockIdx.x * blockDim.x + threadIdx.x;
    if (e >= PE2) return;
    const int s = load_idx(ei, e);
    const int d = load_idx(ei, (size_t)PE2 + e);
    const int t = load_idx(et, e);
    const float w = 1.0f / fmaxf(g_deg2[d], 1.0f);
    const float* ar = att + (size_t)t * PNB;
    __half* base = g_Ah + (size_t)d * PN2 + s;
#pragma unroll
    for (int b = 0; b < PNB; b++)
        atomicAdd(base + ((size_t)b << 20), __float2half_rn(ar[b] * w));
}

// fp16 batched GEMM: S[z] = A[z] @ X. 4-stage cp.async ring, 1 sync/tile.
__global__ __launch_bounds__(256, 2) void gemm1_f16() {
    const int z = blockIdx.z;
    const __half* A = g_Ah + ((size_t)z << 20);
    __half* C = g_Sh + ((size_t)z << 20);
    const int m0 = blockIdx.y * 128, n0 = blockIdx.x * 128;
    __shared__ __half As[4 * STAGE_B / 2];
    __shared__ __half Bs[4 * STAGE_B / 2];
    const int tid = threadIdx.x, lane = tid & 31, warp = tid >> 5;
    const int wm = (warp >> 1) * 32, wn = (warp & 1) * 64;
    const int r = tid >> 1;
    const uint32_t sdst = r * ROW_B + (tid & 1) * 16;    // bytes, 16B-aligned
    const uint32_t AsU = smem_u32(As), BsU = smem_u32(Bs);
    const __half* ap = A + (size_t)(m0 + r) * PN2 + (tid & 1) * 8;
    const __half* bp = g_Xth + (size_t)(n0 + r) * PN2 + (tid & 1) * 8;
    const int base_a = (wm + (lane & 15)) * ROW_B + (lane >> 4) * 16;
    const int base_b = (wn + (lane & 15)) * ROW_B + (lane >> 4) * 16;

    float acc[2][8][4];
#pragma unroll
    for (int i = 0; i < 2; i++)
#pragma unroll
        for (int j = 0; j < 8; j++)
#pragma unroll
            for (int k = 0; k < 4; k++) acc[i][j][k] = 0.0f;

    const int NT = 64;   // 1024 / 16
#pragma unroll
    for (int s = 0; s < 3; s++) {
        cp16(AsU + s * STAGE_B + sdst, ap + s * 16);
        cp16(BsU + s * STAGE_B + sdst, bp + s * 16);
        CP_COMMIT();
    }
#pragma unroll 1
    for (int t = 0; t < NT; t++) {
        CP_WAIT2();
        __syncthreads();
        if (t + 3 < NT) {
            const uint32_t nx = ((t + 3) & 3) * STAGE_B;
            cp16(AsU + nx + sdst, ap + (t + 3) * 16);
            cp16(BsU + nx + sdst, bp + (t + 3) * 16);
            CP_COMMIT();
        }
        const uint32_t cur = (t & 3) * STAGE_B;
        compute_k16(AsU + cur, BsU + cur, base_a, base_b, acc);
    }
#pragma unroll
    for (int mt = 0; mt < 2; mt++)
#pragma unroll
        for (int nt = 0; nt < 8; nt++) {
            const int rr = m0 + wm + mt * 16 + (lane >> 2);
            const int cc = n0 + wn + nt * 8 + (lane & 3) * 2;
            *(__half2*)&C[(size_t)rr * PN2 + cc] =
                __floats2half2_rn(acc[mt][nt][0], acc[mt][nt][1]);
            *(__half2*)&C[(size_t)(rr + 8) * PN2 + cc] =
                __floats2half2_rn(acc[mt][nt][2], acc[mt][nt][3]);
        }
}

// fp16 split-K GEMM: h2 += [S | x_g2] @ [basis ; root]. Same 4-stage ring.
__global__ __launch_bounds__(256, 2) void gemm_acc_f16() {
    const int m0 = blockIdx.y * 128, n0 = blockIdx.x * 128;
    const int kt0 = blockIdx.z * KT_ACC;
    __shared__ __half As[4 * STAGE_B / 2];
    __shared__ __half Bs[4 * STAGE_B / 2];
    const int tid = threadIdx.x, lane = tid & 31, warp = tid >> 5;
    const int wm = (warp >> 1) * 32, wn = (warp & 1) * 64;
    const int r = tid >> 1;
    const uint32_t sdst = r * ROW_B + (tid & 1) * 16;
    const uint32_t AsU = smem_u32(As), BsU = smem_u32(Bs);
    const int base_a = (wm + (lane & 15)) * ROW_B + (lane >> 4) * 16;
    const int base_b = (wn + (lane & 15)) * ROW_B + (lane >> 4) * 16;

    auto srcA = [&](int kt) -> const __half* {
        if (kt < PNB * 64)
            return g_Sh + ((size_t)(kt >> 6) << 20) + (size_t)(m0 + r) * PN2 +
                   ((kt & 63) << 4) + (tid & 1) * 8;
        return g_Xh + (size_t)(m0 + r) * PN2 + ((kt - PNB * 64) << 4) + (tid & 1) * 8;
    };
    auto srcB = [&](int kt) -> const __half* {
        return g_Bth + ((size_t)(kt >> 6) << 20) + (size_t)(n0 + r) * PN2 +
               ((kt & 63) << 4) + (tid & 1) * 8;
    };

    float acc[2][8][4];
#pragma unroll
    for (int i = 0; i < 2; i++)
#pragma unroll
        for (int j = 0; j < 8; j++)
#pragma unroll
            for (int k = 0; k < 4; k++) acc[i][j][k] = 0.0f;

#pragma unroll
    for (int s = 0; s < 3; s++) {
        cp16(AsU + s * STAGE_B + sdst, srcA(kt0 + s));
        cp16(BsU + s * STAGE_B + sdst, srcB(kt0 + s));
        CP_COMMIT();
    }
#pragma unroll 1
    for (int t = 0; t < KT_ACC; t++) {
        CP_WAIT2();
        __syncthreads();
        if (t + 3 < KT_ACC) {
            const uint32_t nx = ((t + 3) & 3) * STAGE_B;
            cp16(AsU + nx + sdst, srcA(kt0 + t + 3));
            cp16(BsU + nx + sdst, srcB(kt0 + t + 3));
            CP_COMMIT();
        }
        const uint32_t cur = (t & 3) * STAGE_B;
        compute_k16(AsU + cur, BsU + cur, base_a, base_b, acc);
    }
#pragma unroll
    for (int mt = 0; mt < 2; mt++)
#pragma unroll
        for (int nt = 0; nt < 8; nt++) {
            const int rr = m0 + wm + mt * 16 + (lane >> 2);
            const int cc = n0 + wn + nt * 8 + (lane & 3) * 2;
            atomicAdd(&g_h2[(size_t)rr * PN2 + cc],           acc[mt][nt][0]);
            atomicAdd(&g_h2[(size_t)rr * PN2 + cc + 1],       acc[mt][nt][1]);
            atomicAdd(&g_h2[(size_t)(rr + 8) * PN2 + cc],     acc[mt][nt][2]);
            atomicAdd(&g_h2[(size_t)(rr + 8) * PN2 + cc + 1], acc[mt][nt][3]);
        }
}

// out2 = log_softmax(relu(h2 + bias)), one block per row
__global__ __launch_bounds__(256) void epilogue2_kernel(const float* __restrict__ bias,
                                                        float* __restrict__ out2) {
    const int row = blockIdx.x, tid = threadIdx.x;
    __shared__ float sred[8];
    __shared__ float sbcast;
    float4 v = *(const float4*)(g_h2 + (size_t)row * PN2 + tid * 4);
    float4 b = *(const float4*)(bias + tid * 4);
    v.x = fmaxf(v.x + b.x, 0.0f);
    v.y = fmaxf(v.y + b.y, 0.0f);
    v.z = fmaxf(v.z + b.z, 0.0f);
    v.w = fmaxf(v.w + b.w, 0.0f);
    float m = fmaxf(fmaxf(v.x, v.y), fmaxf(v.z, v.w));
#pragma unroll
    for (int o = 16; o; o >>= 1) m = fmaxf(m, __shfl_xor_sync(0xffffffffu, m, o));
    if ((tid & 31) == 0) sred[tid >> 5] = m;
    __syncthreads();
    if (tid == 0) {
        float t = sred[0];
#pragma unroll
        for (int i = 1; i < 8; i++) t = fmaxf(t, sred[i]);
        sbcast = t;
    }
    __syncthreads();
    m = sbcast;
    float s = __expf(v.x - m) + __expf(v.y - m) + __expf(v.z - m) + __expf(v.w - m);
#pragma unroll
    for (int o = 16; o; o >>= 1) s += __shfl_xor_sync(0xffffffffu, s, o);
    __syncthreads();
    if ((tid & 31) == 0) sred[tid >> 5] = s;
    __syncthreads();
    if (tid == 0) {
        float t = 0.0f;
#pragma unroll
        for (int i = 0; i < 8; i++) t += sred[i];
        sbcast = m + __logf(t);
    }
    __syncthreads();
    const float lse = sbcast;
    *(float4*)(out2 + (size_t)row * PN2 + tid * 4) =
        make_float4(v.x - lse, v.y - lse, v.z - lse, v.w - lse);
}

// =====================================================================
// launch — kernel launches ONLY. gemm1_f16 is launch index 5 (ncu -s 5).
// =====================================================================
extern "C" void kernel_launch(void* const* d_in, const int* in_sizes, int n_in,
                              void* d_out, int out_size) {
    (void)in_sizes; (void)n_in; (void)out_size;
    const float* x_g1      = (const float*)d_in[0];
    const float* W_stc     = (const float*)d_in[1];
    const float* b_stc     = (const float*)d_in[2];
    const float* x_g2      = (const float*)d_in[3];
    const float* basis     = (const float*)d_in[4];
    const float* att       = (const float*)d_in[5];
    const float* root      = (const float*)d_in[6];
    const float* bias_rgcn = (const float*)d_in[7];
    const void*  ei1       = d_in[8];
    const void*  ei2       = d_in[9];
    const void*  et2       = d_in[10];
    float* out1 = (float*)d_out;
    float* out2 = out1 + (size_t)PN1 * PD;

    dim3 tblk(32, 8);
    probe_kernel<<<1, 256>>>((const int*)ei1);                       // 0
    zero_Ah_kernel<<<15360, 256>>>();                                // 1
    deg2_kernel<<<(PE2 + 255) / 256, 256>>>(ei2);                    // 2
    build_A_f16_kernel<<<(PE2 + 255) / 256, 256>>>(ei2, et2, att);   // 3
    transpose_x_kernel<<<dim3(32, 32), tblk>>>(x_g2);                // 4
    gemm1_f16<<<dim3(8, 8, PNB), 256>>>();                           // 5 <- profiled

    zero_main_kernel<<<12500, 256>>>();                              // 6
    transpose_basis_kernel<<<dim3(32, 32, PNB), tblk>>>(basis);      // 7
    transpose_root_kernel<<<dim3(32, 32), tblk>>>(root);             // 8
    convert_X_kernel<<<512, 256>>>(x_g2);                            // 9

    // ---- Part 1 ----
    scatter1_kernel<<<PE1 / 8, 256>>>(x_g1, ei1);                    // 10
    linear1_kernel<<<(PN1 + 63) / 64, 256>>>(W_stc, b_stc, out1);    // 11

    // ---- Part 2 tail ----
    gemm_acc_f16<<<dim3(8, 8, ZS_ACC), 256>>>();                     // 12
    epilogue2_kernel<<<PN2, 256>>>(bias_rgcn, out2);                 // 13
}

// round 16
// speedup vs baseline: 4.0438x; 1.1048x over previous
#include <cuda_runtime.h>
#include <cuda_fp16.h>
#include <cstdint>

// ---------------- problem dimensions ----------------
#define PN1 100000
#define PE1 1600000
#define PD  128
#define PN2 1024
#define PE2 200000
#define PNB 30
#define ZS_ACC 8
#define KT_ACC 248            // (31744/16) / 8

// GEMM smem rows: 16 halves padded to 48 B
#define ROW_B 48
#define STAGE_B (128 * ROW_B)

// linear1 smem rows: 64 halves padded to 144 B (4r mod 32 conflict-free)
#define LROW_H 72

// ---------------- device scratch ----------------
__device__ __align__(16) float  g_deg1[PN1];
__device__ __align__(16) float  g_agg1[(size_t)PN1 * PD];
__device__ __align__(16) float  g_deg2[PN2];
__device__ __align__(16) float  g_A[(size_t)PNB * PN2 * PN2];      // fp32 atomic build
__device__ __align__(16) __half g_Ah[(size_t)PNB * PN2 * PN2];
__device__ __align__(16) __half g_Sh[(size_t)PNB * PN2 * PN2];
__device__ __align__(16) __half g_Xth[(size_t)PN2 * PN2];
__device__ __align__(16) __half g_Xh[(size_t)PN2 * PN2];
__device__ __align__(16) __half g_Bth[(size_t)(PNB + 1) * PN2 * PN2];
__device__ __align__(16) __half g_Wth[PD * PD];                    // W^T fp16
__device__ __align__(16) float  g_h2[(size_t)PN2 * PN2];
__device__ int g_is64;

// ---------------- helpers ----------------
__device__ __forceinline__ int load_idx(const void* p, size_t idx) {
    if (g_is64) return (int)((const long long*)p)[idx];
    return ((const int*)p)[idx];
}

__device__ __forceinline__ uint32_t smem_u32(const void* p) {
    uint32_t r;
    asm("{ .reg .u64 t; cvta.to.shared.u64 t, %1; cvt.u32.u64 %0, t; }"
        : "=r"(r) : "l"(p));
    return r;
}

__device__ __forceinline__ void ldsm4(uint32_t& r0, uint32_t& r1, uint32_t& r2,
                                      uint32_t& r3, uint32_t addr) {
    asm volatile("ldmatrix.sync.aligned.m8n8.x4.shared.b16 {%0,%1,%2,%3}, [%4];"
                 : "=r"(r0), "=r"(r1), "=r"(r2), "=r"(r3) : "r"(addr));
}

__device__ __forceinline__ void mma_f16(float* c, uint32_t a0, uint32_t a1,
                                        uint32_t a2, uint32_t a3,
                                        uint32_t b0, uint32_t b1) {
    asm volatile(
        "mma.sync.aligned.m16n8k16.row.col.f32.f16.f16.f32 "
        "{%0,%1,%2,%3},{%4,%5,%6,%7},{%8,%9},{%0,%1,%2,%3};"
        : "+f"(c[0]), "+f"(c[1]), "+f"(c[2]), "+f"(c[3])
        : "r"(a0), "r"(a1), "r"(a2), "r"(a3), "r"(b0), "r"(b1));
}

__device__ __forceinline__ void cp16(uint32_t s, const void* g) {
    asm volatile("cp.async.cg.shared.global [%0], [%1], 16;" :: "r"(s), "l"(g));
}
#define CP_COMMIT() asm volatile("cp.async.commit_group;")
#define CP_WAIT2()  asm volatile("cp.async.wait_group 2;")

__device__ __forceinline__ void compute_k16(uint32_t AsU, uint32_t BsU,
                                            int base_a, int base_b,
                                            float (&acc)[2][8][4]) {
    uint32_t a[2][4];
    ldsm4(a[0][0], a[0][1], a[0][2], a[0][3], AsU + base_a);
    ldsm4(a[1][0], a[1][1], a[1][2], a[1][3], AsU + base_a + 16 * ROW_B);
#pragma unroll
    for (int j = 0; j < 4; j++) {
        uint32_t b0, b1, b2, b3;
        ldsm4(b0, b1, b2, b3, BsU + base_b + j * (16 * ROW_B));
        mma_f16(acc[0][2 * j],     a[0][0], a[0][1], a[0][2], a[0][3], b0, b2);
        mma_f16(acc[0][2 * j + 1], a[0][0], a[0][1], a[0][2], a[0][3], b1, b3);
        mma_f16(acc[1][2 * j],     a[1][0], a[1][1], a[1][2], a[1][3], b0, b2);
        mma_f16(acc[1][2 * j + 1], a[1][0], a[1][1], a[1][2], a[1][3], b1, b3);
    }
}

// =====================================================================
// probe / zero / transposes / converts
// =====================================================================
__global__ void probe_kernel(const int* __restrict__ ei_words) {
    __shared__ int found;
    if (threadIdx.x == 0) found = 0;
    __syncthreads();
    for (int i = threadIdx.x; i < 4096; i += 256)
        if (ei_words[2 * i + 1] != 0) found = 1;
    __syncthreads();
    if (threadIdx.x == 0) g_is64 = found ? 0 : 1;
}

__global__ void zero_main_kernel() {
    const size_t i = (size_t)blockIdx.x * blockDim.x + threadIdx.x;
    const float4 z = make_float4(0.f, 0.f, 0.f, 0.f);
    if (i < (size_t)PN1 * PD / 4)  ((float4*)g_agg1)[i] = z;
    if (i < PN1 / 4)               ((float4*)g_deg1)[i] = z;
    if (i < (size_t)PN2 * PN2 / 4) ((float4*)g_h2)[i] = z;
    if (i < PN2 / 4)               ((float4*)g_deg2)[i] = z;
}

__global__ void zero_A_kernel() {
    const size_t i = (size_t)blockIdx.x * blockDim.x + threadIdx.x;
    if (i < ((size_t)PNB << 20) / 4)
        ((float4*)g_A)[i] = make_float4(0.f, 0.f, 0.f, 0.f);
}

__device__ __forceinline__ void transpose_core_h(__half* dst,
                                                 const float* __restrict__ src) {
    __shared__ float tile[32][33];
    int c = blockIdx.x * 32 + threadIdx.x;
    int r = blockIdx.y * 32 + threadIdx.y;
#pragma unroll
    for (int i = 0; i < 32; i += 8)
        tile[threadIdx.y + i][threadIdx.x] = src[(size_t)(r + i) * PN2 + c];
    __syncthreads();
    c = blockIdx.y * 32 + threadIdx.x;
    r = blockIdx.x * 32 + threadIdx.y;
#pragma unroll
    for (int i = 0; i < 32; i += 8)
        dst[(size_t)(r + i) * PN2 + c] = __float2half_rn(tile[threadIdx.x][threadIdx.y + i]);
}

__global__ void transpose_basis_kernel(const float* __restrict__ src) {
    const size_t zoff = (size_t)blockIdx.z << 20;
    transpose_core_h(g_Bth + zoff, src + zoff);
}
__global__ void transpose_root_kernel(const float* __restrict__ src) {
    transpose_core_h(g_Bth + ((size_t)PNB << 20), src);
}
__global__ void transpose_x_kernel(const float* __restrict__ src) {
    transpose_core_h(g_Xth, src);
}

// W [128x128] -> Wth fp16 (W^T)
__global__ void transpose_W_kernel(const float* __restrict__ src) {
    __shared__ float tile[32][33];
    int c = blockIdx.x * 32 + threadIdx.x;
    int r = blockIdx.y * 32 + threadIdx.y;
#pragma unroll
    for (int i = 0; i < 32; i += 8)
        tile[threadIdx.y + i][threadIdx.x] = src[(r + i) * PD + c];
    __syncthreads();
    c = blockIdx.y * 32 + threadIdx.x;
    r = blockIdx.x * 32 + threadIdx.y;
#pragma unroll
    for (int i = 0; i < 32; i += 8)
        g_Wth[(r + i) * PD + c] = __float2half_rn(tile[threadIdx.x][threadIdx.y + i]);
}

__global__ void convert_A_kernel() {
    const size_t i = (size_t)blockIdx.x * blockDim.x + threadIdx.x;
    if (i >= ((size_t)PNB << 20) / 8) return;
    float4 f0 = ((const float4*)g_A)[2 * i];
    float4 f1 = ((const float4*)g_A)[2 * i + 1];
    __half2 h[4];
    h[0] = __floats2half2_rn(f0.x, f0.y);
    h[1] = __floats2half2_rn(f0.z, f0.w);
    h[2] = __floats2half2_rn(f1.x, f1.y);
    h[3] = __floats2half2_rn(f1.z, f1.w);
    ((float4*)g_Ah)[i] = *(float4*)h;
}

__global__ void convert_X_kernel(const float* __restrict__ x) {
    const size_t i = (size_t)blockIdx.x * blockDim.x + threadIdx.x;
    if (i >= ((size_t)PN2 * PN2) / 8) return;
    float4 f0 = ((const float4*)x)[2 * i];
    float4 f1 = ((const float4*)x)[2 * i + 1];
    __half2 h[4];
    h[0] = __floats2half2_rn(f0.x, f0.y);
    h[1] = __floats2half2_rn(f0.z, f0.w);
    h[2] = __floats2half2_rn(f1.x, f1.y);
    h[3] = __floats2half2_rn(f1.z, f1.w);
    ((float4*)g_Xh)[i] = *(float4*)h;
}

// =====================================================================
// Part 1
// =====================================================================
__global__ void scatter1_kernel(const float* __restrict__ x,
                                const void* __restrict__ ei) {
    const unsigned gw = (blockIdx.x * blockDim.x + threadIdx.x) >> 5;
    const int lane = threadIdx.x & 31;
    if (gw >= PE1) return;
    const int s = load_idx(ei, gw);
    const int d = load_idx(ei, (size_t)PE1 + gw);
    float4 v = *(const float4*)(x + (size_t)s * PD + lane * 4);
    float* a = g_agg1 + (size_t)d * PD + lane * 4;
    asm volatile("red.global.add.v4.f32 [%0], {%1,%2,%3,%4};"
                 :: "l"(a), "f"(v.x), "f"(v.y), "f"(v.z), "f"(v.w) : "memory");
    if (lane == 0) atomicAdd(&g_deg1[d], 1.0f);
}

// fp16-MMA linear1 with fused relu + log_softmax.
// Block = 128 rows, 8 warps (4m x 2n), warp tile 32x64, K=128 in 2 chunks.
__global__ __launch_bounds__(256) void linear1_mma(const float* __restrict__ bias,
                                                   float* __restrict__ out1) {
    __shared__ __half As[128 * LROW_H];   // 18 KB
    __shared__ __half Bs[128 * LROW_H];   // 18 KB
    __shared__ float bsm[PD];
    __shared__ float rowmax[2][128];
    __shared__ float rowsum[2][128];
    const int tid = threadIdx.x, lane = tid & 31, warp = tid >> 5;
    const int wm = (warp >> 1) * 32, wn = (warp & 1) * 64;
    const int row0 = blockIdx.x * 128;
    const uint32_t AsU = smem_u32(As), BsU = smem_u32(Bs);
    if (tid < PD) bsm[tid] = bias[tid];

    float acc[2][8][4];
#pragma unroll
    for (int i = 0; i < 2; i++)
#pragma unroll
        for (int j = 0; j < 8; j++)
#pragma unroll
            for (int k = 0; k < 4; k++) acc[i][j][k] = 0.0f;

    const int base_a = (wm + (lane & 15)) * 144 + (lane >> 4) * 16;
    const int base_b = (wn + (lane & 15)) * 144 + (lane >> 4) * 16;

#pragma unroll 1
    for (int kc = 0; kc < 2; kc++) {
        __syncthreads();
        // A: agg/deg -> fp16
#pragma unroll
        for (int it = 0; it < 4; it++) {
            const int task = tid + it * 256;
            const int r = task >> 3, cg = (task & 7) * 8;
            const int grow = row0 + r;
            __half2 h[4];
            if (grow < PN1) {
                const float invd = 1.0f / fmaxf(g_deg1[grow], 1.0f);
                const float* p = g_agg1 + (size_t)grow * PD + kc * 64 + cg;
                float4 f0 = *(const float4*)p, f1 = *(const float4*)(p + 4);
                h[0] = __floats2half2_rn(f0.x * invd, f0.y * invd);
                h[1] = __floats2half2_rn(f0.z * invd, f0.w * invd);
                h[2] = __floats2half2_rn(f1.x * invd, f1.y * invd);
                h[3] = __floats2half2_rn(f1.z * invd, f1.w * invd);
            } else {
                h[0] = h[1] = h[2] = h[3] = __floats2half2_rn(0.f, 0.f);
            }
            *(float4*)&As[r * LROW_H + cg] = *(float4*)h;
        }
        // B: Wth slice
#pragma unroll
        for (int it = 0; it < 4; it++) {
            const int task = tid + it * 256;
            const int n = task >> 3, kg = (task & 7) * 8;
            *(float4*)&Bs[n * LROW_H + kg] =
                *(const float4*)&g_Wth[n * PD + kc * 64 + kg];
        }
        __syncthreads();
#pragma unroll
        for (int ks = 0; ks < 4; ks++) {
            uint32_t a0[4], a1[4];
            ldsm4(a0[0], a0[1], a0[2], a0[3], AsU + base_a + ks * 32);
            ldsm4(a1[0], a1[1], a1[2], a1[3], AsU + base_a + 16 * 144 + ks * 32);
#pragma unroll
            for (int j = 0; j < 4; j++) {
                uint32_t b0, b1, b2, b3;
                ldsm4(b0, b1, b2, b3, BsU + base_b + j * (16 * 144) + ks * 32);
                mma_f16(acc[0][2 * j],     a0[0], a0[1], a0[2], a0[3], b0, b2);
                mma_f16(acc[0][2 * j + 1], a0[0], a0[1], a0[2], a0[3], b1, b3);
                mma_f16(acc[1][2 * j],     a1[0], a1[1], a1[2], a1[3], b0, b2);
                mma_f16(acc[1][2 * j + 1], a1[0], a1[1], a1[2], a1[3], b1, b3);
            }
        }
    }

    // ---- epilogue: bias + relu + log_softmax ----
#pragma unroll
    for (int mt = 0; mt < 2; mt++)
#pragma unroll
        for (int nt = 0; nt < 8; nt++) {
            const int cc = wn + nt * 8 + (lane & 3) * 2;
            const float b0 = bsm[cc], b1 = bsm[cc + 1];
            acc[mt][nt][0] = fmaxf(acc[mt][nt][0] + b0, 0.f);
            acc[mt][nt][1] = fmaxf(acc[mt][nt][1] + b1, 0.f);
            acc[mt][nt][2] = fmaxf(acc[mt][nt][2] + b0, 0.f);
            acc[mt][nt][3] = fmaxf(acc[mt][nt][3] + b1, 0.f);
        }
    float mr[2][2];
#pragma unroll
    for (int mt = 0; mt < 2; mt++) {
        mr[mt][0] = 0.f; mr[mt][1] = 0.f;   // relu'd values >= 0
#pragma unroll
        for (int nt = 0; nt < 8; nt++) {
            mr[mt][0] = fmaxf(mr[mt][0], fmaxf(acc[mt][nt][0], acc[mt][nt][1]));
            mr[mt][1] = fmaxf(mr[mt][1], fmaxf(acc[mt][nt][2], acc[mt][nt][3]));
        }
#pragma unroll
        for (int o = 1; o <= 2; o <<= 1) {
            mr[mt][0] = fmaxf(mr[mt][0], __shfl_xor_sync(0xffffffffu, mr[mt][0], o));
            mr[mt][1] = fmaxf(mr[mt][1], __shfl_xor_sync(0xffffffffu, mr[mt][1], o));
        }
    }
    if ((lane & 3) == 0) {
#pragma unroll
        for (int mt = 0; mt < 2; mt++) {
            rowmax[warp & 1][wm + mt * 16 + (lane >> 2)]     = mr[mt][0];
            rowmax[warp & 1][wm + mt * 16 + (lane >> 2) + 8] = mr[mt][1];
        }
    }
    __syncthreads();
    float M[2][2], sr[2][2];
#pragma unroll
    for (int mt = 0; mt < 2; mt++) {
        const int rb = wm + mt * 16 + (lane >> 2);
        M[mt][0] = fmaxf(rowmax[0][rb], rowmax[1][rb]);
        M[mt][1] = fmaxf(rowmax[0][rb + 8], rowmax[1][rb + 8]);
        sr[mt][0] = 0.f; sr[mt][1] = 0.f;
#pragma unroll
        for (int nt = 0; nt < 8; nt++) {
            sr[mt][0] += __expf(acc[mt][nt][0] - M[mt][0]) +
                         __expf(acc[mt][nt][1] - M[mt][0]);
            sr[mt][1] += __expf(acc[mt][nt][2] - M[mt][1]) +
                         __expf(acc[mt][nt][3] - M[mt][1]);
        }
#pragma unroll
        for (int o = 1; o <= 2; o <<= 1) {
            sr[mt][0] += __shfl_xor_sync(0xffffffffu, sr[mt][0], o);
            sr[mt][1] += __shfl_xor_sync(0xffffffffu, sr[mt][1], o);
        }
    }
    if ((lane & 3) == 0) {
#pragma unroll
        for (int mt = 0; mt < 2; mt++) {
            rowsum[warp & 1][wm + mt * 16 + (lane >> 2)]     = sr[mt][0];
            rowsum[warp & 1][wm + mt * 16 + (lane >> 2) + 8] = sr[mt][1];
        }
    }
    __syncthreads();
#pragma unroll
    for (int mt = 0; mt < 2; mt++) {
        const int rb = wm + mt * 16 + (lane >> 2);
        const float lse0 = M[mt][0] + __logf(rowsum[0][rb] + rowsum[1][rb]);
        const float lse1 = M[mt][1] + __logf(rowsum[0][rb + 8] + rowsum[1][rb + 8]);
        const int r1 = row0 + rb;
#pragma unroll
        for (int nt = 0; nt < 8; nt++) {
            const int cc = wn + nt * 8 + (lane & 3) * 2;
            if (r1 < PN1)
                *(float2*)&out1[(size_t)r1 * PD + cc] =
                    make_float2(acc[mt][nt][0] - lse0, acc[mt][nt][1] - lse0);
            if (r1 + 8 < PN1)
                *(float2*)&out1[(size_t)(r1 + 8) * PD + cc] =
                    make_float2(acc[mt][nt][2] - lse1, acc[mt][nt][3] - lse1);
        }
    }
}

// =====================================================================
// Part 2
// =====================================================================
__global__ void deg2_kernel(const void* __restrict__ ei) {
    int e = blockIdx.x * blockDim.x + threadIdx.x;
    if (e < PE2) atomicAdd(&g_deg2[load_idx(ei, (size_t)PE2 + e)], 1.0f);
}

__global__ void build_A_kernel(const void* __restrict__ ei,
                               const void* __restrict__ et,
                               const float* __restrict__ att) {
    int e = blockIdx.x * blockDim.x + threadIdx.x;
    if (e >= PE2) return;
    const int s = load_idx(ei, e);
    const int d = load_idx(ei, (size_t)PE2 + e);
    const int t = load_idx(et, e);
    const float w = 1.0f / fmaxf(g_deg2[d], 1.0f);
    const float* ar = att + (size_t)t * PNB;
    float* base = g_A + (size_t)d * PN2 + s;
#pragma unroll
    for (int b = 0; b < PNB; b++)
        atomicAdd(base + ((size_t)b << 20), ar[b] * w);
}

__global__ __launch_bounds__(256, 2) void gemm1_f16() {
    const int z = blockIdx.z;
    const __half* A = g_Ah + ((size_t)z << 20);
    __half* C = g_Sh + ((size_t)z << 20);
    const int m0 = blockIdx.y * 128, n0 = blockIdx.x * 128;
    __shared__ __half As[4 * STAGE_B / 2];
    __shared__ __half Bs[4 * STAGE_B / 2];
    const int tid = threadIdx.x, lane = tid & 31, warp = tid >> 5;
    const int wm = (warp >> 1) * 32, wn = (warp & 1) * 64;
    const int r = tid >> 1;
    const uint32_t sdst = r * ROW_B + (tid & 1) * 16;
    const uint32_t AsU = smem_u32(As), BsU = smem_u32(Bs);
    const __half* ap = A + (size_t)(m0 + r) * PN2 + (tid & 1) * 8;
    const __half* bp = g_Xth + (size_t)(n0 + r) * PN2 + (tid & 1) * 8;
    const int base_a = (wm + (lane & 15)) * ROW_B + (lane >> 4) * 16;
    const int base_b = (wn + (lane & 15)) * ROW_B + (lane >> 4) * 16;

    float acc[2][8][4];
#pragma unroll
    for (int i = 0; i < 2; i++)
#pragma unroll
        for (int j = 0; j < 8; j++)
#pragma unroll
            for (int k = 0; k < 4; k++) acc[i][j][k] = 0.0f;

    const int NT = 64;
#pragma unroll
    for (int s = 0; s < 3; s++) {
        cp16(AsU + s * STAGE_B + sdst, ap + s * 16);
        cp16(BsU + s * STAGE_B + sdst, bp + s * 16);
        CP_COMMIT();
    }
#pragma unroll 1
    for (int t = 0; t < NT; t++) {
        CP_WAIT2();
        __syncthreads();
        if (t + 3 < NT) {
            const uint32_t nx = ((t + 3) & 3) * STAGE_B;
            cp16(AsU + nx + sdst, ap + (t + 3) * 16);
            cp16(BsU + nx + sdst, bp + (t + 3) * 16);
            CP_COMMIT();
        }
        const uint32_t cur = (t & 3) * STAGE_B;
        compute_k16(AsU + cur, BsU + cur, base_a, base_b, acc);
    }
#pragma unroll
    for (int mt = 0; mt < 2; mt++)
#pragma unroll
        for (int nt = 0; nt < 8; nt++) {
            const int rr = m0 + wm + mt * 16 + (lane >> 2);
            const int cc = n0 + wn + nt * 8 + (lane & 3) * 2;
            *(__half2*)&C[(size_t)rr * PN2 + cc] =
                __floats2half2_rn(acc[mt][nt][0], acc[mt][nt][1]);
            *(__half2*)&C[(size_t)(rr + 8) * PN2 + cc] =
                __floats2half2_rn(acc[mt][nt][2], acc[mt][nt][3]);
        }
}

__global__ __launch_bounds__(256, 2) void gemm_acc_f16() {
    const int m0 = blockIdx.y * 128, n0 = blockIdx.x * 128;
    const int kt0 = blockIdx.z * KT_ACC;
    __shared__ __half As[4 * STAGE_B / 2];
    __shared__ __half Bs[4 * STAGE_B / 2];
    const int tid = threadIdx.x, lane = tid & 31, warp = tid >> 5;
    const int wm = (warp >> 1) * 32, wn = (warp & 1) * 64;
    const int r = tid >> 1;
    const uint32_t sdst = r * ROW_B + (tid & 1) * 16;
    const uint32_t AsU = smem_u32(As), BsU = smem_u32(Bs);
    const int base_a = (wm + (lane & 15)) * ROW_B + (lane >> 4) * 16;
    const int base_b = (wn + (lane & 15)) * ROW_B + (lane >> 4) * 16;

    auto srcA = [&](int kt) -> const __half* {
        if (kt < PNB * 64)
            return g_Sh + ((size_t)(kt >> 6) << 20) + (size_t)(m0 + r) * PN2 +
                   ((kt & 63) << 4) + (tid & 1) * 8;
        return g_Xh + (size_t)(m0 + r) * PN2 + ((kt - PNB * 64) << 4) + (tid & 1) * 8;
    };
    auto srcB = [&](int kt) -> const __half* {
        return g_Bth + ((size_t)(kt >> 6) << 20) + (size_t)(n0 + r) * PN2 +
               ((kt & 63) << 4) + (tid & 1) * 8;
    };

    float acc[2][8][4];
#pragma unroll
    for (int i = 0; i < 2; i++)
#pragma unroll
        for (int j = 0; j < 8; j++)
#pragma unroll
            for (int k = 0; k < 4; k++) acc[i][j][k] = 0.0f;

#pragma unroll
    for (int s = 0; s < 3; s++) {
        cp16(AsU + s * STAGE_B + sdst, srcA(kt0 + s));
        cp16(BsU + s * STAGE_B + sdst, srcB(kt0 + s));
        CP_COMMIT();
    }
#pragma unroll 1
    for (int t = 0; t < KT_ACC; t++) {
        CP_WAIT2();
        __syncthreads();
        if (t + 3 < KT_ACC) {
            const uint32_t nx = ((t + 3) & 3) * STAGE_B;
            cp16(AsU + nx + sdst, srcA(kt0 + t + 3));
            cp16(BsU + nx + sdst, srcB(kt0 + t + 3));
            CP_COMMIT();
        }
        const uint32_t cur = (t & 3) * STAGE_B;
        compute_k16(AsU + cur, BsU + cur, base_a, base_b, acc);
    }
#pragma unroll
    for (int mt = 0; mt < 2; mt++)
#pragma unroll
        for (int nt = 0; nt < 8; nt++) {
            const int rr = m0 + wm + mt * 16 + (lane >> 2);
            const int cc = n0 + wn + nt * 8 + (lane & 3) * 2;
            atomicAdd(&g_h2[(size_t)rr * PN2 + cc],           acc[mt][nt][0]);
            atomicAdd(&g_h2[(size_t)rr * PN2 + cc + 1],       acc[mt][nt][1]);
            atomicAdd(&g_h2[(size_t)(rr + 8) * PN2 + cc],     acc[mt][nt][2]);
            atomicAdd(&g_h2[(size_t)(rr + 8) * PN2 + cc + 1], acc[mt][nt][3]);
        }
}

__global__ __launch_bounds__(256) void epilogue2_kernel(const float* __restrict__ bias,
                                                        float* __restrict__ out2) {
    const int row = blockIdx.x, tid = threadIdx.x;
    __shared__ float sred[8];
    __shared__ float sbcast;
    float4 v = *(const float4*)(g_h2 + (size_t)row * PN2 + tid * 4);
    float4 b = *(const float4*)(bias + tid * 4);
    v.x = fmaxf(v.x + b.x, 0.0f);
    v.y = fmaxf(v.y + b.y, 0.0f);
    v.z = fmaxf(v.z + b.z, 0.0f);
    v.w = fmaxf(v.w + b.w, 0.0f);
    float m = fmaxf(fmaxf(v.x, v.y), fmaxf(v.z, v.w));
#pragma unroll
    for (int o = 16; o; o >>= 1) m = fmaxf(m, __shfl_xor_sync(0xffffffffu, m, o));
    if ((tid & 31) == 0) sred[tid >> 5] = m;
    __syncthreads();
    if (tid == 0) {
        float t = sred[0];
#pragma unroll
        for (int i = 1; i < 8; i++) t = fmaxf(t, sred[i]);
        sbcast = t;
    }
    __syncthreads();
    m = sbcast;
    float s = __expf(v.x - m) + __expf(v.y - m) + __expf(v.z - m) + __expf(v.w - m);
#pragma unroll
    for (int o = 16; o; o >>= 1) s += __shfl_xor_sync(0xffffffffu, s, o);
    __syncthreads();
    if ((tid & 31) == 0) sred[tid >> 5] = s;
    __syncthreads();
    if (tid == 0) {
        float t = 0.0f;
#pragma unroll
        for (int i = 0; i < 8; i++) t += sred[i];
        sbcast = m + __logf(t);
    }
    __syncthreads();
    const float lse = sbcast;
    *(float4*)(out2 + (size_t)row * PN2 + tid * 4) =
        make_float4(v.x - lse, v.y - lse, v.z - lse, v.w - lse);
}

// =====================================================================
// launch — kernel launches ONLY. scatter1 at index 5 (ncu -s 5).
// =====================================================================
extern "C" void kernel_launch(void* const* d_in, const int* in_sizes, int n_in,
                              void* d_out, int out_size) {
    (void)in_sizes; (void)n_in; (void)out_size;
    const float* x_g1      = (const float*)d_in[0];
    const float* W_stc     = (const float*)d_in[1];
    const float* b_stc     = (const float*)d_in[2];
    const float* x_g2      = (const float*)d_in[3];
    const float* basis     = (const float*)d_in[4];
    const float* att       = (const float*)d_in[5];
    const float* root      = (const float*)d_in[6];
    const float* bias_rgcn = (const float*)d_in[7];
    const void*  ei1       = d_in[8];
    const void*  ei2       = d_in[9];
    const void*  et2       = d_in[10];
    float* out1 = (float*)d_out;
    float* out2 = out1 + (size_t)PN1 * PD;

    dim3 tblk(32, 8);
    probe_kernel<<<1, 256>>>((const int*)ei1);                       // 0
    zero_main_kernel<<<12500, 256>>>();                              // 1
    zero_A_kernel<<<30720, 256>>>();                                 // 2
    deg2_kernel<<<(PE2 + 255) / 256, 256>>>(ei2);                    // 3
    build_A_kernel<<<(PE2 + 255) / 256, 256>>>(ei2, et2, att);       // 4
    scatter1_kernel<<<PE1 / 8, 256>>>(x_g1, ei1);                    // 5 <- profiled

    convert_A_kernel<<<15360, 256>>>();                              // 6
    transpose_x_kernel<<<dim3(32, 32), tblk>>>(x_g2);                // 7
    gemm1_f16<<<dim3(8, 8, PNB), 256>>>();                           // 8
    transpose_basis_kernel<<<dim3(32, 32, PNB), tblk>>>(basis);      // 9
    transpose_root_kernel<<<dim3(32, 32), tblk>>>(root);             // 10
    convert_X_kernel<<<512, 256>>>(x_g2);                            // 11
    transpose_W_kernel<<<dim3(4, 4), tblk>>>(W_stc);                 // 12

    linear1_mma<<<(PN1 + 127) / 128, 256>>>(b_stc, out1);            // 13
    gemm_acc_f16<<<dim3(8, 8, ZS_ACC), 256>>>();                     // 14
    epilogue2_kernel<<<PN2, 256>>>(bias_rgcn, out2);                 // 15
}